// round 5
// baseline (speedup 1.0000x reference)
#include <cuda_runtime.h>
#include <cstdint>
#include <mma.h>
using namespace nvcuda;

#define DIMC   1024
#define HEADS  16
#define HD     64
#define BATCH  512
#define SEQ    65
#define MROWS  (BATCH * SEQ)   // 33280

// Scratch (allocation-free rule: __device__ globals)
__device__ float g_qkv[(size_t)MROWS * 3 * DIMC];  // [B*N, 3*DIM]
__device__ float g_att[(size_t)MROWS * DIMC];      // [B*N, DIM] attention output

// ---------------------------------------------------------------------------
// GEMM: C[M,N] = A[M,K] * B[N,K]^T (both row-major), tf32 WMMA, fp32 accum.
// CTA tile 128x128, 8 warps (4x2), warp tile 32x64 (2x4 frags of 16x16x8).
// 2-stage cp.async double-buffered pipeline. Requires M%128==0, N%128==0,
// K%32==0 (true for all shapes here).
// ---------------------------------------------------------------------------
constexpr int BK  = 32;
constexpr int LDT = 36;            // padded smem leading dim (floats)
constexpr int STG = 256 * LDT;     // floats per stage (A:128 rows + B:128 rows)
#define SMEM_GEMM (2 * STG * 4)    // 73728 bytes

__device__ __forceinline__ void cp_async16(void* smem, const void* gmem) {
    unsigned s = (unsigned)__cvta_generic_to_shared(smem);
    asm volatile("cp.async.cg.shared.global [%0], [%1], 16;\n" ::"r"(s), "l"(gmem));
}

__global__ void __launch_bounds__(256) gemm_bt(const float* __restrict__ A,
                                               const float* __restrict__ B,
                                               float* __restrict__ C,
                                               int M, int N, int K) {
    extern __shared__ __align__(16) float sm[];
    const int tid  = threadIdx.x;
    const int warp = tid >> 5;
    const int wm   = warp >> 1, wn = warp & 1;  // 4 x 2 warp grid
    const int bm   = blockIdx.y * 128, bn = blockIdx.x * 128;

    wmma::fragment<wmma::accumulator, 16, 16, 8, float> acc[2][4];
#pragma unroll
    for (int i = 0; i < 2; i++)
#pragma unroll
        for (int j = 0; j < 4; j++) wmma::fill_fragment(acc[i][j], 0.0f);

    // Per-thread load slots: A tile 128x32 = 1024 float4, B tile same.
    const int lr = tid >> 3;            // row 0..31 (x4 iterations => 128 rows)
    const int lc = (tid & 7) << 2;      // col 0..28 step 4

    auto load_stage = [&](int s, int k0) {
        float* As = sm + s * STG;
        float* Bs = As + 128 * LDT;
#pragma unroll
        for (int i = 0; i < 4; i++) {
            int r = lr + i * 32;
            cp_async16(&As[r * LDT + lc], &A[(size_t)(bm + r) * K + k0 + lc]);
        }
#pragma unroll
        for (int i = 0; i < 4; i++) {
            int r = lr + i * 32;
            cp_async16(&Bs[r * LDT + lc], &B[(size_t)(bn + r) * K + k0 + lc]);
        }
    };

    load_stage(0, 0);
    asm volatile("cp.async.commit_group;\n");

    const int niter = K / BK;
    for (int ks = 0; ks < niter; ks++) {
        if (ks + 1 < niter) load_stage((ks + 1) & 1, (ks + 1) * BK);
        asm volatile("cp.async.commit_group;\n");
        asm volatile("cp.async.wait_group 1;\n");
        __syncthreads();

        const float* As = sm + (ks & 1) * STG;
        const float* Bs = As + 128 * LDT;
#pragma unroll
        for (int kk = 0; kk < BK; kk += 8) {
            wmma::fragment<wmma::matrix_a, 16, 16, 8, wmma::precision::tf32,
                           wmma::row_major> af[2];
            wmma::fragment<wmma::matrix_b, 16, 16, 8, wmma::precision::tf32,
                           wmma::col_major> bf[4];
#pragma unroll
            for (int i = 0; i < 2; i++) {
                wmma::load_matrix_sync(af[i], &As[(wm * 32 + i * 16) * LDT + kk], LDT);
#pragma unroll
                for (int t = 0; t < af[i].num_elements; t++)
                    af[i].x[t] = wmma::__float_to_tf32(af[i].x[t]);
            }
#pragma unroll
            for (int j = 0; j < 4; j++) {
                wmma::load_matrix_sync(bf[j], &Bs[(wn * 64 + j * 16) * LDT + kk], LDT);
#pragma unroll
                for (int t = 0; t < bf[j].num_elements; t++)
                    bf[j].x[t] = wmma::__float_to_tf32(bf[j].x[t]);
            }
#pragma unroll
            for (int i = 0; i < 2; i++)
#pragma unroll
                for (int j = 0; j < 4; j++)
                    wmma::mma_sync(acc[i][j], af[i], bf[j], acc[i][j]);
        }
        __syncthreads();
    }

#pragma unroll
    for (int i = 0; i < 2; i++)
#pragma unroll
        for (int j = 0; j < 4; j++)
            wmma::store_matrix_sync(
                &C[(size_t)(bm + wm * 32 + i * 16) * N + bn + wn * 64 + j * 16],
                acc[i][j], N, wmma::mem_row_major);
}

// ---------------------------------------------------------------------------
// Fused attention: one CTA per (b, h). LN(q)*scale, LN(k), S = qk^T + bias,
// softmax, O = P v.  256 threads. All tiles live in smem; 4x4 register tiling
// on both matmuls; K stored transposed for conflict-free float4 loads.
// Padding: logical 65 padded to 68 (zeroed where it matters).
// ---------------------------------------------------------------------------
#define Q_OFF  0              // q:  [68 rows][stride 68], only d<64 used
#define KV_OFF 4624           // kT: [64 d][stride 68, cols=n] then v: [68 m][stride 68]
#define S_OFF  9248           // s:  [68][68]
#define SMEM_ATT (13872 * 4)  // 55488 bytes

__global__ void __launch_bounds__(256) attn_kernel(
    const float* __restrict__ qkv, const float* __restrict__ bias,
    const float* __restrict__ bscale_p,
    const float* __restrict__ qn_w, const float* __restrict__ qn_b,
    const float* __restrict__ kn_w, const float* __restrict__ kn_b,
    float* __restrict__ outp) {
    extern __shared__ float smf[];
    float* q_s  = smf + Q_OFF;
    float* kv_s = smf + KV_OFF;   // holds kT first, then v
    float* s_s  = smf + S_OFF;

    const int tid = threadIdx.x, lane = tid & 31, warp = tid >> 5;
    const int h = blockIdx.x, b = blockIdx.y;
    const float bscale = *bscale_p;
    const size_t base = (size_t)b * SEQ * 3072 + (size_t)h * 64;

    // Phase 1: load q (row-major, padded rows zero) and k (transposed, padded cols zero)
    for (int i = tid; i < 68 * 64; i += 256) {
        int n = i >> 6, d = i & 63;
        float qv = 0.f, kv = 0.f;
        if (n < SEQ) {
            qv = qkv[base + (size_t)n * 3072 + d];
            kv = qkv[base + (size_t)n * 3072 + 1024 + d];
        }
        q_s[n * 68 + d]  = qv;
        kv_s[d * 68 + n] = kv;   // kT[d][n]
    }
    __syncthreads();

    // Phase 2: LayerNorm rows (q scaled by hd^-0.5)
    const float qw0 = qn_w[lane], qw1 = qn_w[lane + 32];
    const float qb0 = qn_b[lane], qb1 = qn_b[lane + 32];
    const float kw0 = kn_w[lane], kw1 = kn_w[lane + 32];
    const float kb0 = kn_b[lane], kb1 = kn_b[lane + 32];
    for (int n = warp; n < SEQ; n += 8) {
        float x0 = q_s[n * 68 + lane], x1 = q_s[n * 68 + lane + 32];
        float s = x0 + x1, sq = x0 * x0 + x1 * x1;
#pragma unroll
        for (int o = 16; o; o >>= 1) {
            s += __shfl_xor_sync(0xffffffffu, s, o);
            sq += __shfl_xor_sync(0xffffffffu, sq, o);
        }
        float mu = s * (1.f / 64.f);
        float rstd = rsqrtf(sq * (1.f / 64.f) - mu * mu + 1e-5f);
        q_s[n * 68 + lane]      = ((x0 - mu) * rstd * qw0 + qb0) * 0.125f;
        q_s[n * 68 + lane + 32] = ((x1 - mu) * rstd * qw1 + qb1) * 0.125f;

        x0 = kv_s[lane * 68 + n]; x1 = kv_s[(lane + 32) * 68 + n];
        s = x0 + x1; sq = x0 * x0 + x1 * x1;
#pragma unroll
        for (int o = 16; o; o >>= 1) {
            s += __shfl_xor_sync(0xffffffffu, s, o);
            sq += __shfl_xor_sync(0xffffffffu, sq, o);
        }
        mu = s * (1.f / 64.f);
        rstd = rsqrtf(sq * (1.f / 64.f) - mu * mu + 1e-5f);
        kv_s[lane * 68 + n]        = (x0 - mu) * rstd * kw0 + kb0;
        kv_s[(lane + 32) * 68 + n] = (x1 - mu) * rstd * kw1 + kb1;
    }
    __syncthreads();

    // Phase 3: S[n][m] = q[n].k[m] + bias, 4x4 register tiles over 17x17 grid
    for (int idx = tid; idx < 17 * 17; idx += 256) {
        int n0 = (idx / 17) * 4, m0 = (idx % 17) * 4;
        float acc[4][4] = {};
#pragma unroll 8
        for (int d = 0; d < 64; d++) {
            float4 kv4 = *(float4*)&kv_s[d * 68 + m0];  // kT row, conflict-free
            float kvv[4] = {kv4.x, kv4.y, kv4.z, kv4.w};
#pragma unroll
            for (int i = 0; i < 4; i++) {
                float qv = q_s[(n0 + i) * 68 + d];
#pragma unroll
                for (int j = 0; j < 4; j++) acc[i][j] = fmaf(qv, kvv[j], acc[i][j]);
            }
        }
#pragma unroll
        for (int i = 0; i < 4; i++)
#pragma unroll
            for (int j = 0; j < 4; j++) {
                int n = n0 + i, m = m0 + j;
                float bv = (n < SEQ && m < SEQ)
                               ? bias[((size_t)h * SEQ + n) * SEQ + m] * bscale
                               : 0.f;
                s_s[n * 68 + m] = acc[i][j] + bv;  // pad rows/cols get 0
            }
    }
    __syncthreads();

    // Phase 4a: load v into kv_s (row-major stride 68, pad rows zeroed)
    for (int i = tid; i < 68 * 64; i += 256) {
        int n = i >> 6, d = i & 63;
        kv_s[n * 68 + d] =
            (n < SEQ) ? qkv[base + (size_t)n * 3072 + 2048 + d] : 0.f;
    }
    // Phase 4b: softmax rows (strictly over m<65), zero pad cols
    for (int n = warp; n < SEQ; n += 8) {
        float v0 = s_s[n * 68 + lane], v1 = s_s[n * 68 + lane + 32];
        float v2 = (lane == 0) ? s_s[n * 68 + 64] : -3.4e38f;
        float mx = fmaxf(fmaxf(v0, v1), v2);
#pragma unroll
        for (int o = 16; o; o >>= 1) mx = fmaxf(mx, __shfl_xor_sync(0xffffffffu, mx, o));
        float e0 = __expf(v0 - mx), e1 = __expf(v1 - mx);
        float e2 = (lane == 0) ? __expf(v2 - mx) : 0.f;
        float sum = e0 + e1 + e2;
#pragma unroll
        for (int o = 16; o; o >>= 1) sum += __shfl_xor_sync(0xffffffffu, sum, o);
        float inv = 1.f / sum;
        s_s[n * 68 + lane]      = e0 * inv;
        s_s[n * 68 + lane + 32] = e1 * inv;
        if (lane == 0) {
            s_s[n * 68 + 64] = e2 * inv;
            s_s[n * 68 + 65] = 0.f; s_s[n * 68 + 66] = 0.f; s_s[n * 68 + 67] = 0.f;
        }
    }
    __syncthreads();

    // Phase 5: O[n][d] = sum_m P[n][m] * V[m][d], 4x4 tiles over 17x16 grid
    for (int idx = tid; idx < 17 * 16; idx += 256) {
        int n0 = (idx / 16) * 4, d0 = (idx % 16) * 4;
        float acc[4][4] = {};
#pragma unroll 4
        for (int m = 0; m < 68; m++) {
            float4 vv4 = *(float4*)&kv_s[m * 68 + d0];  // conflict-free
            float vvv[4] = {vv4.x, vv4.y, vv4.z, vv4.w};
#pragma unroll
            for (int i = 0; i < 4; i++) {
                float pv = s_s[(n0 + i) * 68 + m];
#pragma unroll
                for (int j = 0; j < 4; j++) acc[i][j] = fmaf(pv, vvv[j], acc[i][j]);
            }
        }
#pragma unroll
        for (int i = 0; i < 4; i++) {
            int n = n0 + i;
            if (n < SEQ) {
                size_t o = ((size_t)b * SEQ + n) * DIMC + (size_t)h * 64 + d0;
#pragma unroll
                for (int j = 0; j < 4; j++) outp[o + j] = acc[i][j];
            }
        }
    }
}

// ---------------------------------------------------------------------------
extern "C" void kernel_launch(void* const* d_in, const int* in_sizes, int n_in,
                              void* d_out, int out_size) {
    const float* x      = (const float*)d_in[0];
    const float* w_qkv  = (const float*)d_in[1];
    const float* w_proj = (const float*)d_in[2];
    const float* qn_w   = (const float*)d_in[3];
    const float* qn_b   = (const float*)d_in[4];
    const float* kn_w   = (const float*)d_in[5];
    const float* kn_b   = (const float*)d_in[6];
    const float* bias   = (const float*)d_in[7];
    const float* bscale = (const float*)d_in[8];
    float* out          = (float*)d_out;

    float* qkv_ptr = nullptr;
    float* att_ptr = nullptr;
    cudaGetSymbolAddress((void**)&qkv_ptr, g_qkv);
    cudaGetSymbolAddress((void**)&att_ptr, g_att);

    cudaFuncSetAttribute(gemm_bt, cudaFuncAttributeMaxDynamicSharedMemorySize,
                         SMEM_GEMM);
    cudaFuncSetAttribute(attn_kernel, cudaFuncAttributeMaxDynamicSharedMemorySize,
                         SMEM_ATT);

    // 1) QKV projection: [33280,1024] x [3072,1024]^T -> [33280,3072]
    gemm_bt<<<dim3(3 * DIMC / 128, MROWS / 128), 256, SMEM_GEMM>>>(
        x, w_qkv, qkv_ptr, MROWS, 3 * DIMC, DIMC);
    // 2) Fused LN + attention per (b,h)
    attn_kernel<<<dim3(HEADS, BATCH), 256, SMEM_ATT>>>(
        qkv_ptr, bias, bscale, qn_w, qn_b, kn_w, kn_b, att_ptr);
    // 3) Output projection: [33280,1024] x [1024,1024]^T -> [33280,1024]
    gemm_bt<<<dim3(DIMC / 128, MROWS / 128), 256, SMEM_GEMM>>>(
        att_ptr, w_proj, out, MROWS, DIMC, DIMC);
}

// round 7
// speedup vs baseline: 1.0429x; 1.0429x over previous
#include <cuda_runtime.h>
#include <cstdint>
#include <mma.h>
using namespace nvcuda;

#define DIMC   1024
#define HEADS  16
#define HD     64
#define BATCH  512
#define SEQ    65
#define MROWS  (BATCH * SEQ)   // 33280 = 260*128

// Scratch (allocation-free rule: __device__ globals)
__device__ float g_qkv[(size_t)MROWS * 3 * DIMC];  // [B*N, 3*DIM]
__device__ float g_att[(size_t)MROWS * DIMC];      // [B*N, DIM] attention output

// ---------------------------------------------------------------------------
// GEMM: C[M,N] = A[M,K] * B[N,K]^T (row-major), tf32 WMMA, fp32 accum.
// CTA tile 128(M) x 64(N), 8 warps (4x2), warp tile 32x32 (2x2 frags 16x16x8).
// 3-stage cp.async ring, ONE __syncthreads per K-iter (loads issued after the
// sync so the stage consumed at iter j-1 is safely overwritten at iter j).
// Requires M%128==0, N%64==0, K%32==0 (true for all shapes here).
// ---------------------------------------------------------------------------
constexpr int TK   = 32;            // K per stage
constexpr int LDT  = 36;            // padded smem leading dim (floats)
constexpr int STGF = 192 * LDT;     // floats per stage: A 128 rows + B 64 rows
#define SMEM_GEMM (3 * STGF * 4)    // 82944 bytes

__device__ __forceinline__ void cp_async16(void* smem, const void* gmem) {
    unsigned s = (unsigned)__cvta_generic_to_shared(smem);
    asm volatile("cp.async.cg.shared.global [%0], [%1], 16;\n" ::"r"(s), "l"(gmem));
}

__global__ void __launch_bounds__(256, 2) gemm_bt(const float* __restrict__ A,
                                                  const float* __restrict__ B,
                                                  float* __restrict__ C,
                                                  int M, int N, int K) {
    extern __shared__ __align__(16) float sm[];
    const int tid  = threadIdx.x;
    const int warp = tid >> 5;
    const int wm   = warp >> 1, wn = warp & 1;  // 4 x 2 warp grid
    const int bm   = blockIdx.y * 128, bn = blockIdx.x * 64;

    wmma::fragment<wmma::accumulator, 16, 16, 8, float> acc[2][2];
#pragma unroll
    for (int i = 0; i < 2; i++)
#pragma unroll
        for (int j = 0; j < 2; j++) wmma::fill_fragment(acc[i][j], 0.0f);

    // Loader: A tile 128x32 = 1024 float4 chunks, B tile 64x32 = 512 chunks.
    const int lrow = tid >> 3;          // 0..31
    const int lcol = (tid & 7) << 2;    // 0,4,..,28

    auto load_stage = [&](int s, int k0) {
        float* As = sm + s * STGF;
        float* Bs = As + 128 * LDT;
#pragma unroll
        for (int t = 0; t < 4; t++) {
            int r = lrow + t * 32;      // 0..127
            cp_async16(&As[r * LDT + lcol], &A[(size_t)(bm + r) * K + k0 + lcol]);
        }
#pragma unroll
        for (int t = 0; t < 2; t++) {
            int r = lrow + t * 32;      // 0..63
            cp_async16(&Bs[r * LDT + lcol], &B[(size_t)(bn + r) * K + k0 + lcol]);
        }
        asm volatile("cp.async.commit_group;\n" ::: "memory");
    };

    load_stage(0, 0);
    load_stage(1, TK);

    const int niter = K / TK;
    for (int j = 0; j < niter; j++) {
        // stage j ready when at most 1 newer group (j+1) is pending
        asm volatile("cp.async.wait_group 1;\n" ::: "memory");
        __syncthreads();
        // prefetch stage j+2 into ring slot (j+2)%3 (its readers done at j-1)
        if (j + 2 < niter) load_stage((j + 2) % 3, (j + 2) * TK);

        const float* As = sm + (j % 3) * STGF;
        const float* Bs = As + 128 * LDT;
#pragma unroll
        for (int kk = 0; kk < TK; kk += 8) {
            wmma::fragment<wmma::matrix_a, 16, 16, 8, wmma::precision::tf32,
                           wmma::row_major> af[2];
            wmma::fragment<wmma::matrix_b, 16, 16, 8, wmma::precision::tf32,
                           wmma::col_major> bf[2];
#pragma unroll
            for (int i = 0; i < 2; i++) {
                wmma::load_matrix_sync(af[i], &As[(wm * 32 + i * 16) * LDT + kk], LDT);
#pragma unroll
                for (int t = 0; t < af[i].num_elements; t++)
                    af[i].x[t] = wmma::__float_to_tf32(af[i].x[t]);
                wmma::load_matrix_sync(bf[i], &Bs[(wn * 32 + i * 16) * LDT + kk], LDT);
#pragma unroll
                for (int t = 0; t < bf[i].num_elements; t++)
                    bf[i].x[t] = wmma::__float_to_tf32(bf[i].x[t]);
            }
#pragma unroll
            for (int i = 0; i < 2; i++)
#pragma unroll
                for (int jj = 0; jj < 2; jj++)
                    wmma::mma_sync(acc[i][jj], af[i], bf[jj], acc[i][jj]);
        }
    }

#pragma unroll
    for (int i = 0; i < 2; i++)
#pragma unroll
        for (int j = 0; j < 2; j++)
            wmma::store_matrix_sync(
                &C[(size_t)(bm + wm * 32 + i * 16) * N + bn + wn * 32 + j * 16],
                acc[i][j], N, wmma::mem_row_major);
}

// ---------------------------------------------------------------------------
// Fused attention: one CTA per (b, h). LN(q)*scale, LN(k), S = qk^T + bias,
// softmax, O = P v.  256 threads; all tiles in smem; 4x4 register tiling.
// ---------------------------------------------------------------------------
#define Q_OFF  0
#define KV_OFF 4624
#define S_OFF  9248
#define SMEM_ATT (13872 * 4)  // 55488 bytes

__global__ void __launch_bounds__(256) attn_kernel(
    const float* __restrict__ qkv, const float* __restrict__ bias,
    const float* __restrict__ bscale_p,
    const float* __restrict__ qn_w, const float* __restrict__ qn_b,
    const float* __restrict__ kn_w, const float* __restrict__ kn_b,
    float* __restrict__ outp) {
    extern __shared__ float smf[];
    float* q_s  = smf + Q_OFF;
    float* kv_s = smf + KV_OFF;
    float* s_s  = smf + S_OFF;

    const int tid = threadIdx.x, lane = tid & 31, warp = tid >> 5;
    const int h = blockIdx.x, b = blockIdx.y;
    const float bscale = *bscale_p;
    const size_t base = (size_t)b * SEQ * 3072 + (size_t)h * 64;

    for (int i = tid; i < 68 * 64; i += 256) {
        int n = i >> 6, d = i & 63;
        float qv = 0.f, kv = 0.f;
        if (n < SEQ) {
            qv = qkv[base + (size_t)n * 3072 + d];
            kv = qkv[base + (size_t)n * 3072 + 1024 + d];
        }
        q_s[n * 68 + d]  = qv;
        kv_s[d * 68 + n] = kv;
    }
    __syncthreads();

    const float qw0 = qn_w[lane], qw1 = qn_w[lane + 32];
    const float qb0 = qn_b[lane], qb1 = qn_b[lane + 32];
    const float kw0 = kn_w[lane], kw1 = kn_w[lane + 32];
    const float kb0 = kn_b[lane], kb1 = kn_b[lane + 32];
    for (int n = warp; n < SEQ; n += 8) {
        float x0 = q_s[n * 68 + lane], x1 = q_s[n * 68 + lane + 32];
        float s = x0 + x1, sq = x0 * x0 + x1 * x1;
#pragma unroll
        for (int o = 16; o; o >>= 1) {
            s += __shfl_xor_sync(0xffffffffu, s, o);
            sq += __shfl_xor_sync(0xffffffffu, sq, o);
        }
        float mu = s * (1.f / 64.f);
        float rstd = rsqrtf(sq * (1.f / 64.f) - mu * mu + 1e-5f);
        q_s[n * 68 + lane]      = ((x0 - mu) * rstd * qw0 + qb0) * 0.125f;
        q_s[n * 68 + lane + 32] = ((x1 - mu) * rstd * qw1 + qb1) * 0.125f;

        x0 = kv_s[lane * 68 + n]; x1 = kv_s[(lane + 32) * 68 + n];
        s = x0 + x1; sq = x0 * x0 + x1 * x1;
#pragma unroll
        for (int o = 16; o; o >>= 1) {
            s += __shfl_xor_sync(0xffffffffu, s, o);
            sq += __shfl_xor_sync(0xffffffffu, sq, o);
        }
        mu = s * (1.f / 64.f);
        rstd = rsqrtf(sq * (1.f / 64.f) - mu * mu + 1e-5f);
        kv_s[lane * 68 + n]        = (x0 - mu) * rstd * kw0 + kb0;
        kv_s[(lane + 32) * 68 + n] = (x1 - mu) * rstd * kw1 + kb1;
    }
    __syncthreads();

    for (int idx = tid; idx < 17 * 17; idx += 256) {
        int n0 = (idx / 17) * 4, m0 = (idx % 17) * 4;
        float acc[4][4] = {};
#pragma unroll 8
        for (int d = 0; d < 64; d++) {
            float4 kv4 = *(float4*)&kv_s[d * 68 + m0];
            float kvv[4] = {kv4.x, kv4.y, kv4.z, kv4.w};
#pragma unroll
            for (int i = 0; i < 4; i++) {
                float qv = q_s[(n0 + i) * 68 + d];
#pragma unroll
                for (int j = 0; j < 4; j++) acc[i][j] = fmaf(qv, kvv[j], acc[i][j]);
            }
        }
#pragma unroll
        for (int i = 0; i < 4; i++)
#pragma unroll
            for (int j = 0; j < 4; j++) {
                int n = n0 + i, m = m0 + j;
                float bv = (n < SEQ && m < SEQ)
                               ? bias[((size_t)h * SEQ + n) * SEQ + m] * bscale
                               : 0.f;
                s_s[n * 68 + m] = acc[i][j] + bv;
            }
    }
    __syncthreads();

    for (int i = tid; i < 68 * 64; i += 256) {
        int n = i >> 6, d = i & 63;
        kv_s[n * 68 + d] =
            (n < SEQ) ? qkv[base + (size_t)n * 3072 + 2048 + d] : 0.f;
    }
    for (int n = warp; n < SEQ; n += 8) {
        float v0 = s_s[n * 68 + lane], v1 = s_s[n * 68 + lane + 32];
        float v2 = (lane == 0) ? s_s[n * 68 + 64] : -3.4e38f;
        float mx = fmaxf(fmaxf(v0, v1), v2);
#pragma unroll
        for (int o = 16; o; o >>= 1) mx = fmaxf(mx, __shfl_xor_sync(0xffffffffu, mx, o));
        float e0 = __expf(v0 - mx), e1 = __expf(v1 - mx);
        float e2 = (lane == 0) ? __expf(v2 - mx) : 0.f;
        float sum = e0 + e1 + e2;
#pragma unroll
        for (int o = 16; o; o >>= 1) sum += __shfl_xor_sync(0xffffffffu, sum, o);
        float inv = 1.f / sum;
        s_s[n * 68 + lane]      = e0 * inv;
        s_s[n * 68 + lane + 32] = e1 * inv;
        if (lane == 0) {
            s_s[n * 68 + 64] = e2 * inv;
            s_s[n * 68 + 65] = 0.f; s_s[n * 68 + 66] = 0.f; s_s[n * 68 + 67] = 0.f;
        }
    }
    __syncthreads();

    for (int idx = tid; idx < 17 * 16; idx += 256) {
        int n0 = (idx / 16) * 4, d0 = (idx % 16) * 4;
        float acc[4][4] = {};
#pragma unroll 4
        for (int m = 0; m < 68; m++) {
            float4 vv4 = *(float4*)&kv_s[m * 68 + d0];
            float vvv[4] = {vv4.x, vv4.y, vv4.z, vv4.w};
#pragma unroll
            for (int i = 0; i < 4; i++) {
                float pv = s_s[(n0 + i) * 68 + m];
#pragma unroll
                for (int j = 0; j < 4; j++) acc[i][j] = fmaf(pv, vvv[j], acc[i][j]);
            }
        }
#pragma unroll
        for (int i = 0; i < 4; i++) {
            int n = n0 + i;
            if (n < SEQ) {
                size_t o = ((size_t)b * SEQ + n) * DIMC + (size_t)h * 64 + d0;
#pragma unroll
                for (int j = 0; j < 4; j++) outp[o + j] = acc[i][j];
            }
        }
    }
}

// ---------------------------------------------------------------------------
extern "C" void kernel_launch(void* const* d_in, const int* in_sizes, int n_in,
                              void* d_out, int out_size) {
    const float* x      = (const float*)d_in[0];
    const float* w_qkv  = (const float*)d_in[1];
    const float* w_proj = (const float*)d_in[2];
    const float* qn_w   = (const float*)d_in[3];
    const float* qn_b   = (const float*)d_in[4];
    const float* kn_w   = (const float*)d_in[5];
    const float* kn_b   = (const float*)d_in[6];
    const float* bias   = (const float*)d_in[7];
    const float* bscale = (const float*)d_in[8];
    float* out          = (float*)d_out;

    float* qkv_ptr = nullptr;
    float* att_ptr = nullptr;
    cudaGetSymbolAddress((void**)&qkv_ptr, g_qkv);
    cudaGetSymbolAddress((void**)&att_ptr, g_att);

    cudaFuncSetAttribute(gemm_bt, cudaFuncAttributeMaxDynamicSharedMemorySize,
                         SMEM_GEMM);
    cudaFuncSetAttribute(attn_kernel, cudaFuncAttributeMaxDynamicSharedMemorySize,
                         SMEM_ATT);

    // 1) QKV projection: [33280,1024] x [3072,1024]^T -> [33280,3072]
    gemm_bt<<<dim3(3 * DIMC / 64, MROWS / 128), 256, SMEM_GEMM>>>(
        x, w_qkv, qkv_ptr, MROWS, 3 * DIMC, DIMC);
    // 2) Fused LN + attention per (b,h)
    attn_kernel<<<dim3(HEADS, BATCH), 256, SMEM_ATT>>>(
        qkv_ptr, bias, bscale, qn_w, qn_b, kn_w, kn_b, att_ptr);
    // 3) Output projection: [33280,1024] x [1024,1024]^T -> [33280,1024]
    gemm_bt<<<dim3(DIMC / 64, MROWS / 128), 256, SMEM_GEMM>>>(
        att_ptr, w_proj, out, MROWS, DIMC, DIMC);
}

// round 8
// speedup vs baseline: 1.0812x; 1.0367x over previous
#include <cuda_runtime.h>
#include <cstdint>
#include <mma.h>
using namespace nvcuda;

#define DIMC   1024
#define HEADS  16
#define HD     64
#define BATCH  512
#define SEQ    65
#define MROWS  (BATCH * SEQ)   // 33280 = 260*128

// Scratch (allocation-free rule: __device__ globals)
__device__ float g_qkv[(size_t)MROWS * 3 * DIMC];   // GEMM1 out
__device__ float g_att[(size_t)MROWS * DIMC];       // attention out (tf32-rounded)
__device__ float g_xr[(size_t)MROWS * DIMC];        // x rounded to tf32
__device__ float g_wqkvr[(size_t)3 * DIMC * DIMC];  // w_qkv rounded
__device__ float g_wprojr[(size_t)DIMC * DIMC];     // w_proj rounded

// ---------------------------------------------------------------------------
// tf32 round-to-nearest (RN) helper + bulk pre-round kernel
// ---------------------------------------------------------------------------
__device__ __forceinline__ float tf32r(float x) {
    unsigned u;
    asm("cvt.rn.tf32.f32 %0, %1;" : "=r"(u) : "f"(x));
    return __uint_as_float(u);
}

__global__ void __launch_bounds__(256) round_tf32_k(const float* __restrict__ in,
                                                    float* __restrict__ out, int n4) {
    int i = blockIdx.x * blockDim.x + threadIdx.x;
    if (i < n4) {
        float4 v = ((const float4*)in)[i];
        v.x = tf32r(v.x); v.y = tf32r(v.y); v.z = tf32r(v.z); v.w = tf32r(v.w);
        ((float4*)out)[i] = v;
    }
}

// ---------------------------------------------------------------------------
// GEMM: C[M,N] = A[M,K] * B[N,K]^T (row-major), tf32 WMMA, fp32 accum.
// INPUTS MUST BE PRE-ROUNDED TO TF32 — no per-fragment converts in the loop.
// CTA tile 128(M) x 64(N), 8 warps (4x2), warp tile 32x32.
// 3-stage cp.async ring, one __syncthreads per K-iter.
// ---------------------------------------------------------------------------
constexpr int TK   = 32;            // K per stage
constexpr int LDT  = 36;            // padded smem leading dim (floats)
constexpr int STGF = 192 * LDT;     // floats per stage: A 128 rows + B 64 rows
#define SMEM_GEMM (3 * STGF * 4)    // 82944 bytes

__device__ __forceinline__ void cp_async16(void* smem, const void* gmem) {
    unsigned s = (unsigned)__cvta_generic_to_shared(smem);
    asm volatile("cp.async.cg.shared.global [%0], [%1], 16;\n" ::"r"(s), "l"(gmem));
}

__global__ void __launch_bounds__(256, 2) gemm_bt(const float* __restrict__ A,
                                                  const float* __restrict__ B,
                                                  float* __restrict__ C,
                                                  int M, int N, int K) {
    extern __shared__ __align__(16) float sm[];
    const int tid  = threadIdx.x;
    const int warp = tid >> 5;
    const int wm   = warp >> 1, wn = warp & 1;  // 4 x 2 warp grid
    const int bm   = blockIdx.y * 128, bn = blockIdx.x * 64;

    wmma::fragment<wmma::accumulator, 16, 16, 8, float> acc[2][2];
#pragma unroll
    for (int i = 0; i < 2; i++)
#pragma unroll
        for (int j = 0; j < 2; j++) wmma::fill_fragment(acc[i][j], 0.0f);

    const int lrow = tid >> 3;          // 0..31
    const int lcol = (tid & 7) << 2;    // 0,4,..,28

    auto load_stage = [&](int s, int k0) {
        float* As = sm + s * STGF;
        float* Bs = As + 128 * LDT;
#pragma unroll
        for (int t = 0; t < 4; t++) {
            int r = lrow + t * 32;      // 0..127
            cp_async16(&As[r * LDT + lcol], &A[(size_t)(bm + r) * K + k0 + lcol]);
        }
#pragma unroll
        for (int t = 0; t < 2; t++) {
            int r = lrow + t * 32;      // 0..63
            cp_async16(&Bs[r * LDT + lcol], &B[(size_t)(bn + r) * K + k0 + lcol]);
        }
        asm volatile("cp.async.commit_group;\n" ::: "memory");
    };

    load_stage(0, 0);
    load_stage(1, TK);

    const int niter = K / TK;
    for (int j = 0; j < niter; j++) {
        asm volatile("cp.async.wait_group 1;\n" ::: "memory");
        __syncthreads();
        if (j + 2 < niter) load_stage((j + 2) % 3, (j + 2) * TK);

        const float* As = sm + (j % 3) * STGF;
        const float* Bs = As + 128 * LDT;
#pragma unroll
        for (int kk = 0; kk < TK; kk += 8) {
            wmma::fragment<wmma::matrix_a, 16, 16, 8, wmma::precision::tf32,
                           wmma::row_major> af[2];
            wmma::fragment<wmma::matrix_b, 16, 16, 8, wmma::precision::tf32,
                           wmma::col_major> bf[2];
            // Data already tf32-rounded in gmem -> NO per-element converts.
#pragma unroll
            for (int i = 0; i < 2; i++) {
                wmma::load_matrix_sync(af[i], &As[(wm * 32 + i * 16) * LDT + kk], LDT);
                wmma::load_matrix_sync(bf[i], &Bs[(wn * 32 + i * 16) * LDT + kk], LDT);
            }
#pragma unroll
            for (int i = 0; i < 2; i++)
#pragma unroll
                for (int jj = 0; jj < 2; jj++)
                    wmma::mma_sync(acc[i][jj], af[i], bf[jj], acc[i][jj]);
        }
    }

#pragma unroll
    for (int i = 0; i < 2; i++)
#pragma unroll
        for (int j = 0; j < 2; j++)
            wmma::store_matrix_sync(
                &C[(size_t)(bm + wm * 32 + i * 16) * N + bn + wn * 32 + j * 16],
                acc[i][j], N, wmma::mem_row_major);
}

// ---------------------------------------------------------------------------
// Fused attention: one CTA per (b, h). LN(q)*scale, LN(k), S = qk^T + bias,
// softmax, O = P v. Epilogue rounds output to tf32 (feeds GEMM2 directly).
// ---------------------------------------------------------------------------
#define Q_OFF  0
#define KV_OFF 4624
#define S_OFF  9248
#define SMEM_ATT (13872 * 4)  // 55488 bytes

__global__ void __launch_bounds__(256) attn_kernel(
    const float* __restrict__ qkv, const float* __restrict__ bias,
    const float* __restrict__ bscale_p,
    const float* __restrict__ qn_w, const float* __restrict__ qn_b,
    const float* __restrict__ kn_w, const float* __restrict__ kn_b,
    float* __restrict__ outp) {
    extern __shared__ float smf[];
    float* q_s  = smf + Q_OFF;
    float* kv_s = smf + KV_OFF;
    float* s_s  = smf + S_OFF;

    const int tid = threadIdx.x, lane = tid & 31, warp = tid >> 5;
    const int h = blockIdx.x, b = blockIdx.y;
    const float bscale = *bscale_p;
    const size_t base = (size_t)b * SEQ * 3072 + (size_t)h * 64;

    for (int i = tid; i < 68 * 64; i += 256) {
        int n = i >> 6, d = i & 63;
        float qv = 0.f, kv = 0.f;
        if (n < SEQ) {
            qv = qkv[base + (size_t)n * 3072 + d];
            kv = qkv[base + (size_t)n * 3072 + 1024 + d];
        }
        q_s[n * 68 + d]  = qv;
        kv_s[d * 68 + n] = kv;
    }
    __syncthreads();

    const float qw0 = qn_w[lane], qw1 = qn_w[lane + 32];
    const float qb0 = qn_b[lane], qb1 = qn_b[lane + 32];
    const float kw0 = kn_w[lane], kw1 = kn_w[lane + 32];
    const float kb0 = kn_b[lane], kb1 = kn_b[lane + 32];
    for (int n = warp; n < SEQ; n += 8) {
        float x0 = q_s[n * 68 + lane], x1 = q_s[n * 68 + lane + 32];
        float s = x0 + x1, sq = x0 * x0 + x1 * x1;
#pragma unroll
        for (int o = 16; o; o >>= 1) {
            s += __shfl_xor_sync(0xffffffffu, s, o);
            sq += __shfl_xor_sync(0xffffffffu, sq, o);
        }
        float mu = s * (1.f / 64.f);
        float rstd = rsqrtf(sq * (1.f / 64.f) - mu * mu + 1e-5f);
        q_s[n * 68 + lane]      = ((x0 - mu) * rstd * qw0 + qb0) * 0.125f;
        q_s[n * 68 + lane + 32] = ((x1 - mu) * rstd * qw1 + qb1) * 0.125f;

        x0 = kv_s[lane * 68 + n]; x1 = kv_s[(lane + 32) * 68 + n];
        s = x0 + x1; sq = x0 * x0 + x1 * x1;
#pragma unroll
        for (int o = 16; o; o >>= 1) {
            s += __shfl_xor_sync(0xffffffffu, s, o);
            sq += __shfl_xor_sync(0xffffffffu, sq, o);
        }
        mu = s * (1.f / 64.f);
        rstd = rsqrtf(sq * (1.f / 64.f) - mu * mu + 1e-5f);
        kv_s[lane * 68 + n]        = (x0 - mu) * rstd * kw0 + kb0;
        kv_s[(lane + 32) * 68 + n] = (x1 - mu) * rstd * kw1 + kb1;
    }
    __syncthreads();

    for (int idx = tid; idx < 17 * 17; idx += 256) {
        int n0 = (idx / 17) * 4, m0 = (idx % 17) * 4;
        float acc[4][4] = {};
#pragma unroll 8
        for (int d = 0; d < 64; d++) {
            float4 kv4 = *(float4*)&kv_s[d * 68 + m0];
            float kvv[4] = {kv4.x, kv4.y, kv4.z, kv4.w};
#pragma unroll
            for (int i = 0; i < 4; i++) {
                float qv = q_s[(n0 + i) * 68 + d];
#pragma unroll
                for (int j = 0; j < 4; j++) acc[i][j] = fmaf(qv, kvv[j], acc[i][j]);
            }
        }
#pragma unroll
        for (int i = 0; i < 4; i++)
#pragma unroll
            for (int j = 0; j < 4; j++) {
                int n = n0 + i, m = m0 + j;
                float bv = (n < SEQ && m < SEQ)
                               ? bias[((size_t)h * SEQ + n) * SEQ + m] * bscale
                               : 0.f;
                s_s[n * 68 + m] = acc[i][j] + bv;
            }
    }
    __syncthreads();

    for (int i = tid; i < 68 * 64; i += 256) {
        int n = i >> 6, d = i & 63;
        kv_s[n * 68 + d] =
            (n < SEQ) ? qkv[base + (size_t)n * 3072 + 2048 + d] : 0.f;
    }
    for (int n = warp; n < SEQ; n += 8) {
        float v0 = s_s[n * 68 + lane], v1 = s_s[n * 68 + lane + 32];
        float v2 = (lane == 0) ? s_s[n * 68 + 64] : -3.4e38f;
        float mx = fmaxf(fmaxf(v0, v1), v2);
#pragma unroll
        for (int o = 16; o; o >>= 1) mx = fmaxf(mx, __shfl_xor_sync(0xffffffffu, mx, o));
        float e0 = __expf(v0 - mx), e1 = __expf(v1 - mx);
        float e2 = (lane == 0) ? __expf(v2 - mx) : 0.f;
        float sum = e0 + e1 + e2;
#pragma unroll
        for (int o = 16; o; o >>= 1) sum += __shfl_xor_sync(0xffffffffu, sum, o);
        float inv = 1.f / sum;
        s_s[n * 68 + lane]      = e0 * inv;
        s_s[n * 68 + lane + 32] = e1 * inv;
        if (lane == 0) {
            s_s[n * 68 + 64] = e2 * inv;
            s_s[n * 68 + 65] = 0.f; s_s[n * 68 + 66] = 0.f; s_s[n * 68 + 67] = 0.f;
        }
    }
    __syncthreads();

    for (int idx = tid; idx < 17 * 16; idx += 256) {
        int n0 = (idx / 16) * 4, d0 = (idx % 16) * 4;
        float acc[4][4] = {};
#pragma unroll 4
        for (int m = 0; m < 68; m++) {
            float4 vv4 = *(float4*)&kv_s[m * 68 + d0];
            float vvv[4] = {vv4.x, vv4.y, vv4.z, vv4.w};
#pragma unroll
            for (int i = 0; i < 4; i++) {
                float pv = s_s[(n0 + i) * 68 + m];
#pragma unroll
                for (int j = 0; j < 4; j++) acc[i][j] = fmaf(pv, vvv[j], acc[i][j]);
            }
        }
#pragma unroll
        for (int i = 0; i < 4; i++) {
            int n = n0 + i;
            if (n < SEQ) {
                size_t o = ((size_t)b * SEQ + n) * DIMC + (size_t)h * 64 + d0;
#pragma unroll
                for (int j = 0; j < 4; j++) outp[o + j] = tf32r(acc[i][j]);
            }
        }
    }
}

// ---------------------------------------------------------------------------
extern "C" void kernel_launch(void* const* d_in, const int* in_sizes, int n_in,
                              void* d_out, int out_size) {
    const float* x      = (const float*)d_in[0];
    const float* w_qkv  = (const float*)d_in[1];
    const float* w_proj = (const float*)d_in[2];
    const float* qn_w   = (const float*)d_in[3];
    const float* qn_b   = (const float*)d_in[4];
    const float* kn_w   = (const float*)d_in[5];
    const float* kn_b   = (const float*)d_in[6];
    const float* bias   = (const float*)d_in[7];
    const float* bscale = (const float*)d_in[8];
    float* out          = (float*)d_out;

    float *qkv_p, *att_p, *xr_p, *wqkvr_p, *wprojr_p;
    cudaGetSymbolAddress((void**)&qkv_p, g_qkv);
    cudaGetSymbolAddress((void**)&att_p, g_att);
    cudaGetSymbolAddress((void**)&xr_p, g_xr);
    cudaGetSymbolAddress((void**)&wqkvr_p, g_wqkvr);
    cudaGetSymbolAddress((void**)&wprojr_p, g_wprojr);

    cudaFuncSetAttribute(gemm_bt, cudaFuncAttributeMaxDynamicSharedMemorySize,
                         SMEM_GEMM);
    cudaFuncSetAttribute(attn_kernel, cudaFuncAttributeMaxDynamicSharedMemorySize,
                         SMEM_ATT);

    // 0) pre-round operands to tf32 (RN) once; GEMM loop then has zero converts
    int n4x = MROWS * DIMC / 4;
    round_tf32_k<<<(n4x + 255) / 256, 256>>>(x, xr_p, n4x);
    int n4wq = 3 * DIMC * DIMC / 4;
    round_tf32_k<<<(n4wq + 255) / 256, 256>>>(w_qkv, wqkvr_p, n4wq);
    int n4wp = DIMC * DIMC / 4;
    round_tf32_k<<<(n4wp + 255) / 256, 256>>>(w_proj, wprojr_p, n4wp);

    // 1) QKV projection: [33280,1024] x [3072,1024]^T -> [33280,3072]
    gemm_bt<<<dim3(3 * DIMC / 64, MROWS / 128), 256, SMEM_GEMM>>>(
        xr_p, wqkvr_p, qkv_p, MROWS, 3 * DIMC, DIMC);
    // 2) Fused LN + attention per (b,h); writes tf32-rounded output
    attn_kernel<<<dim3(HEADS, BATCH), 256, SMEM_ATT>>>(
        qkv_p, bias, bscale, qn_w, qn_b, kn_w, kn_b, att_p);
    // 3) Output projection: [33280,1024] x [1024,1024]^T -> [33280,1024]
    gemm_bt<<<dim3(DIMC / 64, MROWS / 128), 256, SMEM_GEMM>>>(
        att_p, wprojr_p, out, MROWS, DIMC, DIMC);
}

// round 10
// speedup vs baseline: 2.1103x; 1.9518x over previous
#include <cuda_runtime.h>
#include <cuda_fp16.h>
#include <cstdint>
#include <mma.h>
using namespace nvcuda;

#define DIMC   1024
#define HEADS  16
#define HD     64
#define BATCH  512
#define SEQ    65
#define MROWS  (BATCH * SEQ)   // 33280 = 260*128

// Scratch (allocation-free rule: __device__ globals)
__device__ float  g_qkv[(size_t)MROWS * 3 * DIMC];    // GEMM1 out (fp32)
__device__ float  g_att[(size_t)MROWS * DIMC];        // attn out (tf32-rounded)
__device__ __half g_xh[(size_t)MROWS * DIMC];         // x -> half
__device__ __half g_wqkvh[(size_t)3 * DIMC * DIMC];   // w_qkv -> half
__device__ float  g_wprojr[(size_t)DIMC * DIMC];      // w_proj -> tf32-rounded

// ---------------------------------------------------------------------------
// converts
// ---------------------------------------------------------------------------
__device__ __forceinline__ float tf32r(float x) {
    unsigned u;
    asm("cvt.rn.tf32.f32 %0, %1;" : "=r"(u) : "f"(x));
    return __uint_as_float(u);
}

__global__ void __launch_bounds__(256) f2h_k(const float4* __restrict__ in,
                                             __half2* __restrict__ out, int n4) {
    int i = blockIdx.x * blockDim.x + threadIdx.x;
    if (i < n4) {
        float4 v = in[i];
        out[2 * i]     = __floats2half2_rn(v.x, v.y);
        out[2 * i + 1] = __floats2half2_rn(v.z, v.w);
    }
}

__global__ void __launch_bounds__(256) round_tf32_k(const float* __restrict__ in,
                                                    float* __restrict__ out, int n4) {
    int i = blockIdx.x * blockDim.x + threadIdx.x;
    if (i < n4) {
        float4 v = ((const float4*)in)[i];
        v.x = tf32r(v.x); v.y = tf32r(v.y); v.z = tf32r(v.z); v.w = tf32r(v.w);
        ((float4*)out)[i] = v;
    }
}

__device__ __forceinline__ void cp_async16(void* smem, const void* gmem) {
    unsigned s = (unsigned)__cvta_generic_to_shared(smem);
    asm volatile("cp.async.cg.shared.global [%0], [%1], 16;\n" ::"r"(s), "l"(gmem));
}

// ---------------------------------------------------------------------------
// GEMM1: fp16 WMMA m16n16k16, fp32 acc. C = A[M,K] * B[N,K]^T.
// CTA tile 128x64, 8 warps (4x2). 3-stage cp.async ring, K=64/stage.
// ---------------------------------------------------------------------------
constexpr int TKH  = 64;             // K halfs per stage (=128B rows)
constexpr int LDTH = 72;             // padded smem leading dim (halfs)
constexpr int STGH = 192 * LDTH;     // halfs/stage: A 128 rows + B 64 rows
#define SMEM_GH (3 * STGH * 2)       // 82944 bytes

__global__ void __launch_bounds__(256, 2) gemm_h(const __half* __restrict__ A,
                                                 const __half* __restrict__ B,
                                                 float* __restrict__ C,
                                                 int M, int N, int K) {
    extern __shared__ __align__(16) __half smh[];
    const int tid  = threadIdx.x;
    const int warp = tid >> 5;
    const int wm   = warp >> 1, wn = warp & 1;
    const int bm   = blockIdx.y * 128, bn = blockIdx.x * 64;

    wmma::fragment<wmma::accumulator, 16, 16, 16, float> acc[2][2];
#pragma unroll
    for (int i = 0; i < 2; i++)
#pragma unroll
        for (int j = 0; j < 2; j++) wmma::fill_fragment(acc[i][j], 0.0f);

    const int lrow = tid >> 3;          // 0..31
    const int lcol = (tid & 7) << 3;    // 0,8,..,56 halfs (16B)

    auto load_stage = [&](int s, int k0) {
        __half* As = smh + s * STGH;
        __half* Bs = As + 128 * LDTH;
#pragma unroll
        for (int t = 0; t < 4; t++) {
            int r = lrow + t * 32;
            cp_async16(&As[r * LDTH + lcol], &A[(size_t)(bm + r) * K + k0 + lcol]);
        }
#pragma unroll
        for (int t = 0; t < 2; t++) {
            int r = lrow + t * 32;
            cp_async16(&Bs[r * LDTH + lcol], &B[(size_t)(bn + r) * K + k0 + lcol]);
        }
        asm volatile("cp.async.commit_group;\n" ::: "memory");
    };

    load_stage(0, 0);
    load_stage(1, TKH);

    const int niter = K / TKH;   // 16
    for (int j = 0; j < niter; j++) {
        asm volatile("cp.async.wait_group 1;\n" ::: "memory");
        __syncthreads();
        if (j + 2 < niter) load_stage((j + 2) % 3, (j + 2) * TKH);

        const __half* As = smh + (j % 3) * STGH;
        const __half* Bs = As + 128 * LDTH;
#pragma unroll
        for (int kk = 0; kk < TKH; kk += 16) {
            wmma::fragment<wmma::matrix_a, 16, 16, 16, __half, wmma::row_major> af[2];
            wmma::fragment<wmma::matrix_b, 16, 16, 16, __half, wmma::col_major> bf[2];
#pragma unroll
            for (int i = 0; i < 2; i++) {
                wmma::load_matrix_sync(af[i], &As[(wm * 32 + i * 16) * LDTH + kk], LDTH);
                wmma::load_matrix_sync(bf[i], &Bs[(wn * 32 + i * 16) * LDTH + kk], LDTH);
            }
#pragma unroll
            for (int i = 0; i < 2; i++)
#pragma unroll
                for (int jj = 0; jj < 2; jj++)
                    wmma::mma_sync(acc[i][jj], af[i], bf[jj], acc[i][jj]);
        }
    }

#pragma unroll
    for (int i = 0; i < 2; i++)
#pragma unroll
        for (int j = 0; j < 2; j++)
            wmma::store_matrix_sync(
                &C[(size_t)(bm + wm * 32 + i * 16) * N + bn + wn * 32 + j * 16],
                acc[i][j], N, wmma::mem_row_major);
}

// ---------------------------------------------------------------------------
// GEMM2: tf32 WMMA (pre-rounded inputs, no in-loop converts), fp32 acc.
// CTA tile 128x64, 8 warps, 3-stage cp.async ring, K=32/stage.
// ---------------------------------------------------------------------------
constexpr int TKF  = 32;
constexpr int LDTF = 36;
constexpr int STGF = 192 * LDTF;
#define SMEM_GT (3 * STGF * 4)       // 82944 bytes

__global__ void __launch_bounds__(256, 2) gemm_bt(const float* __restrict__ A,
                                                  const float* __restrict__ B,
                                                  float* __restrict__ C,
                                                  int M, int N, int K) {
    extern __shared__ __align__(16) float smf2[];
    const int tid  = threadIdx.x;
    const int warp = tid >> 5;
    const int wm   = warp >> 1, wn = warp & 1;
    const int bm   = blockIdx.y * 128, bn = blockIdx.x * 64;

    wmma::fragment<wmma::accumulator, 16, 16, 8, float> acc[2][2];
#pragma unroll
    for (int i = 0; i < 2; i++)
#pragma unroll
        for (int j = 0; j < 2; j++) wmma::fill_fragment(acc[i][j], 0.0f);

    const int lrow = tid >> 3;
    const int lcol = (tid & 7) << 2;

    auto load_stage = [&](int s, int k0) {
        float* As = smf2 + s * STGF;
        float* Bs = As + 128 * LDTF;
#pragma unroll
        for (int t = 0; t < 4; t++) {
            int r = lrow + t * 32;
            cp_async16(&As[r * LDTF + lcol], &A[(size_t)(bm + r) * K + k0 + lcol]);
        }
#pragma unroll
        for (int t = 0; t < 2; t++) {
            int r = lrow + t * 32;
            cp_async16(&Bs[r * LDTF + lcol], &B[(size_t)(bn + r) * K + k0 + lcol]);
        }
        asm volatile("cp.async.commit_group;\n" ::: "memory");
    };

    load_stage(0, 0);
    load_stage(1, TKF);

    const int niter = K / TKF;
    for (int j = 0; j < niter; j++) {
        asm volatile("cp.async.wait_group 1;\n" ::: "memory");
        __syncthreads();
        if (j + 2 < niter) load_stage((j + 2) % 3, (j + 2) * TKF);

        const float* As = smf2 + (j % 3) * STGF;
        const float* Bs = As + 128 * LDTF;
#pragma unroll
        for (int kk = 0; kk < TKF; kk += 8) {
            wmma::fragment<wmma::matrix_a, 16, 16, 8, wmma::precision::tf32,
                           wmma::row_major> af[2];
            wmma::fragment<wmma::matrix_b, 16, 16, 8, wmma::precision::tf32,
                           wmma::col_major> bf[2];
#pragma unroll
            for (int i = 0; i < 2; i++) {
                wmma::load_matrix_sync(af[i], &As[(wm * 32 + i * 16) * LDTF + kk], LDTF);
                wmma::load_matrix_sync(bf[i], &Bs[(wn * 32 + i * 16) * LDTF + kk], LDTF);
            }
#pragma unroll
            for (int i = 0; i < 2; i++)
#pragma unroll
                for (int jj = 0; jj < 2; jj++)
                    wmma::mma_sync(acc[i][jj], af[i], bf[jj], acc[i][jj]);
        }
    }

#pragma unroll
    for (int i = 0; i < 2; i++)
#pragma unroll
        for (int j = 0; j < 2; j++)
            wmma::store_matrix_sync(
                &C[(size_t)(bm + wm * 32 + i * 16) * N + bn + wn * 32 + j * 16],
                acc[i][j], N, wmma::mem_row_major);
}

// ---------------------------------------------------------------------------
// Fused attention (unchanged): LN, QK^T+bias, softmax, PV.
// Epilogue rounds to tf32 (feeds tf32 GEMM2).
// ---------------------------------------------------------------------------
#define Q_OFF  0
#define KV_OFF 4624
#define S_OFF  9248
#define SMEM_ATT (13872 * 4)  // 55488 bytes

__global__ void __launch_bounds__(256) attn_kernel(
    const float* __restrict__ qkv, const float* __restrict__ bias,
    const float* __restrict__ bscale_p,
    const float* __restrict__ qn_w, const float* __restrict__ qn_b,
    const float* __restrict__ kn_w, const float* __restrict__ kn_b,
    float* __restrict__ outp) {
    extern __shared__ float smf[];
    float* q_s  = smf + Q_OFF;
    float* kv_s = smf + KV_OFF;
    float* s_s  = smf + S_OFF;

    const int tid = threadIdx.x, lane = tid & 31, warp = tid >> 5;
    const int h = blockIdx.x, b = blockIdx.y;
    const float bscale = *bscale_p;
    const size_t base = (size_t)b * SEQ * 3072 + (size_t)h * 64;

    for (int i = tid; i < 68 * 64; i += 256) {
        int n = i >> 6, d = i & 63;
        float qv = 0.f, kv = 0.f;
        if (n < SEQ) {
            qv = qkv[base + (size_t)n * 3072 + d];
            kv = qkv[base + (size_t)n * 3072 + 1024 + d];
        }
        q_s[n * 68 + d]  = qv;
        kv_s[d * 68 + n] = kv;
    }
    __syncthreads();

    const float qw0 = qn_w[lane], qw1 = qn_w[lane + 32];
    const float qb0 = qn_b[lane], qb1 = qn_b[lane + 32];
    const float kw0 = kn_w[lane], kw1 = kn_w[lane + 32];
    const float kb0 = kn_b[lane], kb1 = kn_b[lane + 32];
    for (int n = warp; n < SEQ; n += 8) {
        float x0 = q_s[n * 68 + lane], x1 = q_s[n * 68 + lane + 32];
        float s = x0 + x1, sq = x0 * x0 + x1 * x1;
#pragma unroll
        for (int o = 16; o; o >>= 1) {
            s += __shfl_xor_sync(0xffffffffu, s, o);
            sq += __shfl_xor_sync(0xffffffffu, sq, o);
        }
        float mu = s * (1.f / 64.f);
        float rstd = rsqrtf(sq * (1.f / 64.f) - mu * mu + 1e-5f);
        q_s[n * 68 + lane]      = ((x0 - mu) * rstd * qw0 + qb0) * 0.125f;
        q_s[n * 68 + lane + 32] = ((x1 - mu) * rstd * qw1 + qb1) * 0.125f;

        x0 = kv_s[lane * 68 + n]; x1 = kv_s[(lane + 32) * 68 + n];
        s = x0 + x1; sq = x0 * x0 + x1 * x1;
#pragma unroll
        for (int o = 16; o; o >>= 1) {
            s += __shfl_xor_sync(0xffffffffu, s, o);
            sq += __shfl_xor_sync(0xffffffffu, sq, o);
        }
        mu = s * (1.f / 64.f);
        rstd = rsqrtf(sq * (1.f / 64.f) - mu * mu + 1e-5f);
        kv_s[lane * 68 + n]        = (x0 - mu) * rstd * kw0 + kb0;
        kv_s[(lane + 32) * 68 + n] = (x1 - mu) * rstd * kw1 + kb1;
    }
    __syncthreads();

    for (int idx = tid; idx < 17 * 17; idx += 256) {
        int n0 = (idx / 17) * 4, m0 = (idx % 17) * 4;
        float acc[4][4] = {};
#pragma unroll 8
        for (int d = 0; d < 64; d++) {
            float4 kv4 = *(float4*)&kv_s[d * 68 + m0];
            float kvv[4] = {kv4.x, kv4.y, kv4.z, kv4.w};
#pragma unroll
            for (int i = 0; i < 4; i++) {
                float qv = q_s[(n0 + i) * 68 + d];
#pragma unroll
                for (int j = 0; j < 4; j++) acc[i][j] = fmaf(qv, kvv[j], acc[i][j]);
            }
        }
#pragma unroll
        for (int i = 0; i < 4; i++)
#pragma unroll
            for (int j = 0; j < 4; j++) {
                int n = n0 + i, m = m0 + j;
                float bv = (n < SEQ && m < SEQ)
                               ? bias[((size_t)h * SEQ + n) * SEQ + m] * bscale
                               : 0.f;
                s_s[n * 68 + m] = acc[i][j] + bv;
            }
    }
    __syncthreads();

    for (int i = tid; i < 68 * 64; i += 256) {
        int n = i >> 6, d = i & 63;
        kv_s[n * 68 + d] =
            (n < SEQ) ? qkv[base + (size_t)n * 3072 + 2048 + d] : 0.f;
    }
    for (int n = warp; n < SEQ; n += 8) {
        float v0 = s_s[n * 68 + lane], v1 = s_s[n * 68 + lane + 32];
        float v2 = (lane == 0) ? s_s[n * 68 + 64] : -3.4e38f;
        float mx = fmaxf(fmaxf(v0, v1), v2);
#pragma unroll
        for (int o = 16; o; o >>= 1) mx = fmaxf(mx, __shfl_xor_sync(0xffffffffu, mx, o));
        float e0 = __expf(v0 - mx), e1 = __expf(v1 - mx);
        float e2 = (lane == 0) ? __expf(v2 - mx) : 0.f;
        float sum = e0 + e1 + e2;
#pragma unroll
        for (int o = 16; o; o >>= 1) sum += __shfl_xor_sync(0xffffffffu, sum, o);
        float inv = 1.f / sum;
        s_s[n * 68 + lane]      = e0 * inv;
        s_s[n * 68 + lane + 32] = e1 * inv;
        if (lane == 0) {
            s_s[n * 68 + 64] = e2 * inv;
            s_s[n * 68 + 65] = 0.f; s_s[n * 68 + 66] = 0.f; s_s[n * 68 + 67] = 0.f;
        }
    }
    __syncthreads();

    for (int idx = tid; idx < 17 * 16; idx += 256) {
        int n0 = (idx / 16) * 4, d0 = (idx % 16) * 4;
        float acc[4][4] = {};
#pragma unroll 4
        for (int m = 0; m < 68; m++) {
            float4 vv4 = *(float4*)&kv_s[m * 68 + d0];
            float vvv[4] = {vv4.x, vv4.y, vv4.z, vv4.w};
#pragma unroll
            for (int i = 0; i < 4; i++) {
                float pv = s_s[(n0 + i) * 68 + m];
#pragma unroll
                for (int j = 0; j < 4; j++) acc[i][j] = fmaf(pv, vvv[j], acc[i][j]);
            }
        }
#pragma unroll
        for (int i = 0; i < 4; i++) {
            int n = n0 + i;
            if (n < SEQ) {
                size_t o = ((size_t)b * SEQ + n) * DIMC + (size_t)h * 64 + d0;
#pragma unroll
                for (int j = 0; j < 4; j++) outp[o + j] = tf32r(acc[i][j]);
            }
        }
    }
}

// ---------------------------------------------------------------------------
extern "C" void kernel_launch(void* const* d_in, const int* in_sizes, int n_in,
                              void* d_out, int out_size) {
    const float* x      = (const float*)d_in[0];
    const float* w_qkv  = (const float*)d_in[1];
    const float* w_proj = (const float*)d_in[2];
    const float* qn_w   = (const float*)d_in[3];
    const float* qn_b   = (const float*)d_in[4];
    const float* kn_w   = (const float*)d_in[5];
    const float* kn_b   = (const float*)d_in[6];
    const float* bias   = (const float*)d_in[7];
    const float* bscale = (const float*)d_in[8];
    float* out          = (float*)d_out;

    float *qkv_p, *att_p, *wprojr_p;
    __half *xh_p, *wqkvh_p;
    cudaGetSymbolAddress((void**)&qkv_p, g_qkv);
    cudaGetSymbolAddress((void**)&att_p, g_att);
    cudaGetSymbolAddress((void**)&xh_p, g_xh);
    cudaGetSymbolAddress((void**)&wqkvh_p, g_wqkvh);
    cudaGetSymbolAddress((void**)&wprojr_p, g_wprojr);

    cudaFuncSetAttribute(gemm_h, cudaFuncAttributeMaxDynamicSharedMemorySize,
                         SMEM_GH);
    cudaFuncSetAttribute(gemm_bt, cudaFuncAttributeMaxDynamicSharedMemorySize,
                         SMEM_GT);
    cudaFuncSetAttribute(attn_kernel, cudaFuncAttributeMaxDynamicSharedMemorySize,
                         SMEM_ATT);

    // 0) operand converts: fp16 for GEMM1, tf32 for GEMM2 weights
    int n4x = MROWS * DIMC / 4;
    f2h_k<<<(n4x + 255) / 256, 256>>>((const float4*)x, (__half2*)xh_p, n4x);
    int n4wq = 3 * DIMC * DIMC / 4;
    f2h_k<<<(n4wq + 255) / 256, 256>>>((const float4*)w_qkv, (__half2*)wqkvh_p, n4wq);
    int n4wp = DIMC * DIMC / 4;
    round_tf32_k<<<(n4wp + 255) / 256, 256>>>(w_proj, wprojr_p, n4wp);

    // 1) QKV projection (fp16 tensor): [33280,1024] x [3072,1024]^T
    gemm_h<<<dim3(3 * DIMC / 64, MROWS / 128), 256, SMEM_GH>>>(
        xh_p, wqkvh_p, qkv_p, MROWS, 3 * DIMC, DIMC);
    // 2) Fused LN + attention per (b,h); emits tf32-rounded fp32
    attn_kernel<<<dim3(HEADS, BATCH), 256, SMEM_ATT>>>(
        qkv_p, bias, bscale, qn_w, qn_b, kn_w, kn_b, att_p);
    // 3) Output projection (tf32 tensor): [33280,1024] x [1024,1024]^T
    gemm_bt<<<dim3(DIMC / 64, MROWS / 128), 256, SMEM_GT>>>(
        att_p, wprojr_p, out, MROWS, DIMC, DIMC);
}

// round 11
// speedup vs baseline: 2.2685x; 1.0750x over previous
#include <cuda_runtime.h>
#include <cuda_fp16.h>
#include <cstdint>
#include <mma.h>
using namespace nvcuda;

#define DIMC   1024
#define HEADS  16
#define HD     64
#define BATCH  512
#define SEQ    65
#define MROWS  (BATCH * SEQ)   // 33280 = 260*128

// Scratch (allocation-free rule: __device__ globals)
__device__ float  g_qkv[(size_t)MROWS * 3 * DIMC];    // GEMM1 out (fp32)
__device__ float  g_att[(size_t)MROWS * DIMC];        // attn out (tf32-rounded)
__device__ __half g_xh[(size_t)MROWS * DIMC];         // x -> half
__device__ __half g_wqkvh[(size_t)3 * DIMC * DIMC];   // w_qkv -> half
__device__ float  g_wprojr[(size_t)DIMC * DIMC];      // w_proj -> tf32-rounded

// ---------------------------------------------------------------------------
// converts
// ---------------------------------------------------------------------------
__device__ __forceinline__ float tf32r(float x) {
    unsigned u;
    asm("cvt.rn.tf32.f32 %0, %1;" : "=r"(u) : "f"(x));
    return __uint_as_float(u);
}

__global__ void __launch_bounds__(256) f2h_k(const float4* __restrict__ in,
                                             __half2* __restrict__ out, int n4) {
    int i = blockIdx.x * blockDim.x + threadIdx.x;
    if (i < n4) {
        float4 v = in[i];
        out[2 * i]     = __floats2half2_rn(v.x, v.y);
        out[2 * i + 1] = __floats2half2_rn(v.z, v.w);
    }
}

__global__ void __launch_bounds__(256) round_tf32_k(const float* __restrict__ in,
                                                    float* __restrict__ out, int n4) {
    int i = blockIdx.x * blockDim.x + threadIdx.x;
    if (i < n4) {
        float4 v = ((const float4*)in)[i];
        v.x = tf32r(v.x); v.y = tf32r(v.y); v.z = tf32r(v.z); v.w = tf32r(v.w);
        ((float4*)out)[i] = v;
    }
}

__device__ __forceinline__ void cp_async16(void* smem, const void* gmem) {
    unsigned s = (unsigned)__cvta_generic_to_shared(smem);
    asm volatile("cp.async.cg.shared.global [%0], [%1], 16;\n" ::"r"(s), "l"(gmem));
}

// ---------------------------------------------------------------------------
// GEMM1: fp16 WMMA m16n16k16, fp32 acc. C = A[M,K] * B[N,K]^T.
// CTA 128x128, 8 warps (4Mx2N), warp tile 32x64 (2x4 frags).
// 2-stage cp.async ring, K=64/stage (128B rows). 2 CTAs/SM.
// ---------------------------------------------------------------------------
constexpr int TKH  = 64;             // K halfs per stage
constexpr int LDTH = 72;             // padded leading dim (halfs, 144B)
constexpr int STGH = 256 * LDTH;     // halfs/stage: A 128 + B 128 rows
#define SMEM_GH (2 * STGH * 2)       // 73728 bytes

__global__ void __launch_bounds__(256, 2) gemm_h(const __half* __restrict__ A,
                                                 const __half* __restrict__ B,
                                                 float* __restrict__ C,
                                                 int M, int N, int K) {
    extern __shared__ __align__(16) __half smh[];
    const int tid  = threadIdx.x;
    const int warp = tid >> 5;
    const int wm   = warp >> 1, wn = warp & 1;   // 4 x 2
    const int bm   = blockIdx.y * 128, bn = blockIdx.x * 128;

    wmma::fragment<wmma::accumulator, 16, 16, 16, float> acc[2][4];
#pragma unroll
    for (int i = 0; i < 2; i++)
#pragma unroll
        for (int j = 0; j < 4; j++) wmma::fill_fragment(acc[i][j], 0.0f);

    const int lrow = tid >> 3;          // 0..31
    const int lcol = (tid & 7) << 3;    // 0..56 halfs (16B chunks)

    auto load_stage = [&](int s, int k0) {
        __half* As = smh + s * STGH;
        __half* Bs = As + 128 * LDTH;
#pragma unroll
        for (int t = 0; t < 4; t++) {
            int r = lrow + t * 32;
            cp_async16(&As[r * LDTH + lcol], &A[(size_t)(bm + r) * K + k0 + lcol]);
        }
#pragma unroll
        for (int t = 0; t < 4; t++) {
            int r = lrow + t * 32;
            cp_async16(&Bs[r * LDTH + lcol], &B[(size_t)(bn + r) * K + k0 + lcol]);
        }
        asm volatile("cp.async.commit_group;\n" ::: "memory");
    };

    load_stage(0, 0);

    const int niter = K / TKH;   // 16
    for (int j = 0; j < niter; j++) {
        if (j + 1 < niter) load_stage((j + 1) & 1, (j + 1) * TKH);
        else asm volatile("cp.async.commit_group;\n" ::: "memory");
        asm volatile("cp.async.wait_group 1;\n" ::: "memory");
        __syncthreads();

        const __half* As = smh + (j & 1) * STGH;
        const __half* Bs = As + 128 * LDTH;
#pragma unroll
        for (int kk = 0; kk < TKH; kk += 16) {
            wmma::fragment<wmma::matrix_a, 16, 16, 16, __half, wmma::row_major> af[2];
            wmma::fragment<wmma::matrix_b, 16, 16, 16, __half, wmma::col_major> bf[4];
#pragma unroll
            for (int i = 0; i < 2; i++)
                wmma::load_matrix_sync(af[i], &As[(wm * 32 + i * 16) * LDTH + kk], LDTH);
#pragma unroll
            for (int jj = 0; jj < 4; jj++)
                wmma::load_matrix_sync(bf[jj], &Bs[(wn * 64 + jj * 16) * LDTH + kk], LDTH);
#pragma unroll
            for (int i = 0; i < 2; i++)
#pragma unroll
                for (int jj = 0; jj < 4; jj++)
                    wmma::mma_sync(acc[i][jj], af[i], bf[jj], acc[i][jj]);
        }
        __syncthreads();
    }

#pragma unroll
    for (int i = 0; i < 2; i++)
#pragma unroll
        for (int j = 0; j < 4; j++)
            wmma::store_matrix_sync(
                &C[(size_t)(bm + wm * 32 + i * 16) * N + bn + wn * 64 + j * 16],
                acc[i][j], N, wmma::mem_row_major);
}

// ---------------------------------------------------------------------------
// GEMM2: tf32 WMMA (pre-rounded inputs), fp32 acc.
// CTA 128x128, 8 warps (4Mx2N), warp tile 32x64. 2-stage ring, K=32/stage.
// ---------------------------------------------------------------------------
constexpr int TKF  = 32;
constexpr int LDTF = 36;             // 144B rows
constexpr int STGF = 256 * LDTF;
#define SMEM_GT (2 * STGF * 4)       // 73728 bytes

__global__ void __launch_bounds__(256, 2) gemm_bt(const float* __restrict__ A,
                                                  const float* __restrict__ B,
                                                  float* __restrict__ C,
                                                  int M, int N, int K) {
    extern __shared__ __align__(16) float smf2[];
    const int tid  = threadIdx.x;
    const int warp = tid >> 5;
    const int wm   = warp >> 1, wn = warp & 1;
    const int bm   = blockIdx.y * 128, bn = blockIdx.x * 128;

    wmma::fragment<wmma::accumulator, 16, 16, 8, float> acc[2][4];
#pragma unroll
    for (int i = 0; i < 2; i++)
#pragma unroll
        for (int j = 0; j < 4; j++) wmma::fill_fragment(acc[i][j], 0.0f);

    const int lrow = tid >> 3;
    const int lcol = (tid & 7) << 2;    // floats (16B chunks)

    auto load_stage = [&](int s, int k0) {
        float* As = smf2 + s * STGF;
        float* Bs = As + 128 * LDTF;
#pragma unroll
        for (int t = 0; t < 4; t++) {
            int r = lrow + t * 32;
            cp_async16(&As[r * LDTF + lcol], &A[(size_t)(bm + r) * K + k0 + lcol]);
        }
#pragma unroll
        for (int t = 0; t < 4; t++) {
            int r = lrow + t * 32;
            cp_async16(&Bs[r * LDTF + lcol], &B[(size_t)(bn + r) * K + k0 + lcol]);
        }
        asm volatile("cp.async.commit_group;\n" ::: "memory");
    };

    load_stage(0, 0);

    const int niter = K / TKF;   // 32
    for (int j = 0; j < niter; j++) {
        if (j + 1 < niter) load_stage((j + 1) & 1, (j + 1) * TKF);
        else asm volatile("cp.async.commit_group;\n" ::: "memory");
        asm volatile("cp.async.wait_group 1;\n" ::: "memory");
        __syncthreads();

        const float* As = smf2 + (j & 1) * STGF;
        const float* Bs = As + 128 * LDTF;
#pragma unroll
        for (int kk = 0; kk < TKF; kk += 8) {
            wmma::fragment<wmma::matrix_a, 16, 16, 8, wmma::precision::tf32,
                           wmma::row_major> af[2];
            wmma::fragment<wmma::matrix_b, 16, 16, 8, wmma::precision::tf32,
                           wmma::col_major> bf[4];
#pragma unroll
            for (int i = 0; i < 2; i++)
                wmma::load_matrix_sync(af[i], &As[(wm * 32 + i * 16) * LDTF + kk], LDTF);
#pragma unroll
            for (int jj = 0; jj < 4; jj++)
                wmma::load_matrix_sync(bf[jj], &Bs[(wn * 64 + jj * 16) * LDTF + kk], LDTF);
#pragma unroll
            for (int i = 0; i < 2; i++)
#pragma unroll
                for (int jj = 0; jj < 4; jj++)
                    wmma::mma_sync(acc[i][jj], af[i], bf[jj], acc[i][jj]);
        }
        __syncthreads();
    }

#pragma unroll
    for (int i = 0; i < 2; i++)
#pragma unroll
        for (int j = 0; j < 4; j++)
            wmma::store_matrix_sync(
                &C[(size_t)(bm + wm * 32 + i * 16) * N + bn + wn * 64 + j * 16],
                acc[i][j], N, wmma::mem_row_major);
}

// ---------------------------------------------------------------------------
// Fused attention (unchanged): LN, QK^T+bias, softmax, PV.
// Epilogue rounds to tf32 (feeds tf32 GEMM2).
// ---------------------------------------------------------------------------
#define Q_OFF  0
#define KV_OFF 4624
#define S_OFF  9248
#define SMEM_ATT (13872 * 4)  // 55488 bytes

__global__ void __launch_bounds__(256) attn_kernel(
    const float* __restrict__ qkv, const float* __restrict__ bias,
    const float* __restrict__ bscale_p,
    const float* __restrict__ qn_w, const float* __restrict__ qn_b,
    const float* __restrict__ kn_w, const float* __restrict__ kn_b,
    float* __restrict__ outp) {
    extern __shared__ float smf[];
    float* q_s  = smf + Q_OFF;
    float* kv_s = smf + KV_OFF;
    float* s_s  = smf + S_OFF;

    const int tid = threadIdx.x, lane = tid & 31, warp = tid >> 5;
    const int h = blockIdx.x, b = blockIdx.y;
    const float bscale = *bscale_p;
    const size_t base = (size_t)b * SEQ * 3072 + (size_t)h * 64;

    for (int i = tid; i < 68 * 64; i += 256) {
        int n = i >> 6, d = i & 63;
        float qv = 0.f, kv = 0.f;
        if (n < SEQ) {
            qv = qkv[base + (size_t)n * 3072 + d];
            kv = qkv[base + (size_t)n * 3072 + 1024 + d];
        }
        q_s[n * 68 + d]  = qv;
        kv_s[d * 68 + n] = kv;
    }
    __syncthreads();

    const float qw0 = qn_w[lane], qw1 = qn_w[lane + 32];
    const float qb0 = qn_b[lane], qb1 = qn_b[lane + 32];
    const float kw0 = kn_w[lane], kw1 = kn_w[lane + 32];
    const float kb0 = kn_b[lane], kb1 = kn_b[lane + 32];
    for (int n = warp; n < SEQ; n += 8) {
        float x0 = q_s[n * 68 + lane], x1 = q_s[n * 68 + lane + 32];
        float s = x0 + x1, sq = x0 * x0 + x1 * x1;
#pragma unroll
        for (int o = 16; o; o >>= 1) {
            s += __shfl_xor_sync(0xffffffffu, s, o);
            sq += __shfl_xor_sync(0xffffffffu, sq, o);
        }
        float mu = s * (1.f / 64.f);
        float rstd = rsqrtf(sq * (1.f / 64.f) - mu * mu + 1e-5f);
        q_s[n * 68 + lane]      = ((x0 - mu) * rstd * qw0 + qb0) * 0.125f;
        q_s[n * 68 + lane + 32] = ((x1 - mu) * rstd * qw1 + qb1) * 0.125f;

        x0 = kv_s[lane * 68 + n]; x1 = kv_s[(lane + 32) * 68 + n];
        s = x0 + x1; sq = x0 * x0 + x1 * x1;
#pragma unroll
        for (int o = 16; o; o >>= 1) {
            s += __shfl_xor_sync(0xffffffffu, s, o);
            sq += __shfl_xor_sync(0xffffffffu, sq, o);
        }
        mu = s * (1.f / 64.f);
        rstd = rsqrtf(sq * (1.f / 64.f) - mu * mu + 1e-5f);
        kv_s[lane * 68 + n]        = (x0 - mu) * rstd * kw0 + kb0;
        kv_s[(lane + 32) * 68 + n] = (x1 - mu) * rstd * kw1 + kb1;
    }
    __syncthreads();

    for (int idx = tid; idx < 17 * 17; idx += 256) {
        int n0 = (idx / 17) * 4, m0 = (idx % 17) * 4;
        float acc[4][4] = {};
#pragma unroll 8
        for (int d = 0; d < 64; d++) {
            float4 kv4 = *(float4*)&kv_s[d * 68 + m0];
            float kvv[4] = {kv4.x, kv4.y, kv4.z, kv4.w};
#pragma unroll
            for (int i = 0; i < 4; i++) {
                float qv = q_s[(n0 + i) * 68 + d];
#pragma unroll
                for (int j = 0; j < 4; j++) acc[i][j] = fmaf(qv, kvv[j], acc[i][j]);
            }
        }
#pragma unroll
        for (int i = 0; i < 4; i++)
#pragma unroll
            for (int j = 0; j < 4; j++) {
                int n = n0 + i, m = m0 + j;
                float bv = (n < SEQ && m < SEQ)
                               ? bias[((size_t)h * SEQ + n) * SEQ + m] * bscale
                               : 0.f;
                s_s[n * 68 + m] = acc[i][j] + bv;
            }
    }
    __syncthreads();

    for (int i = tid; i < 68 * 64; i += 256) {
        int n = i >> 6, d = i & 63;
        kv_s[n * 68 + d] =
            (n < SEQ) ? qkv[base + (size_t)n * 3072 + 2048 + d] : 0.f;
    }
    for (int n = warp; n < SEQ; n += 8) {
        float v0 = s_s[n * 68 + lane], v1 = s_s[n * 68 + lane + 32];
        float v2 = (lane == 0) ? s_s[n * 68 + 64] : -3.4e38f;
        float mx = fmaxf(fmaxf(v0, v1), v2);
#pragma unroll
        for (int o = 16; o; o >>= 1) mx = fmaxf(mx, __shfl_xor_sync(0xffffffffu, mx, o));
        float e0 = __expf(v0 - mx), e1 = __expf(v1 - mx);
        float e2 = (lane == 0) ? __expf(v2 - mx) : 0.f;
        float sum = e0 + e1 + e2;
#pragma unroll
        for (int o = 16; o; o >>= 1) sum += __shfl_xor_sync(0xffffffffu, sum, o);
        float inv = 1.f / sum;
        s_s[n * 68 + lane]      = e0 * inv;
        s_s[n * 68 + lane + 32] = e1 * inv;
        if (lane == 0) {
            s_s[n * 68 + 64] = e2 * inv;
            s_s[n * 68 + 65] = 0.f; s_s[n * 68 + 66] = 0.f; s_s[n * 68 + 67] = 0.f;
        }
    }
    __syncthreads();

    for (int idx = tid; idx < 17 * 16; idx += 256) {
        int n0 = (idx / 16) * 4, d0 = (idx % 16) * 4;
        float acc[4][4] = {};
#pragma unroll 4
        for (int m = 0; m < 68; m++) {
            float4 vv4 = *(float4*)&kv_s[m * 68 + d0];
            float vvv[4] = {vv4.x, vv4.y, vv4.z, vv4.w};
#pragma unroll
            for (int i = 0; i < 4; i++) {
                float pv = s_s[(n0 + i) * 68 + m];
#pragma unroll
                for (int j = 0; j < 4; j++) acc[i][j] = fmaf(pv, vvv[j], acc[i][j]);
            }
        }
#pragma unroll
        for (int i = 0; i < 4; i++) {
            int n = n0 + i;
            if (n < SEQ) {
                size_t o = ((size_t)b * SEQ + n) * DIMC + (size_t)h * 64 + d0;
#pragma unroll
                for (int j = 0; j < 4; j++) outp[o + j] = tf32r(acc[i][j]);
            }
        }
    }
}

// ---------------------------------------------------------------------------
extern "C" void kernel_launch(void* const* d_in, const int* in_sizes, int n_in,
                              void* d_out, int out_size) {
    const float* x      = (const float*)d_in[0];
    const float* w_qkv  = (const float*)d_in[1];
    const float* w_proj = (const float*)d_in[2];
    const float* qn_w   = (const float*)d_in[3];
    const float* qn_b   = (const float*)d_in[4];
    const float* kn_w   = (const float*)d_in[5];
    const float* kn_b   = (const float*)d_in[6];
    const float* bias   = (const float*)d_in[7];
    const float* bscale = (const float*)d_in[8];
    float* out          = (float*)d_out;

    float *qkv_p, *att_p, *wprojr_p;
    __half *xh_p, *wqkvh_p;
    cudaGetSymbolAddress((void**)&qkv_p, g_qkv);
    cudaGetSymbolAddress((void**)&att_p, g_att);
    cudaGetSymbolAddress((void**)&xh_p, g_xh);
    cudaGetSymbolAddress((void**)&wqkvh_p, g_wqkvh);
    cudaGetSymbolAddress((void**)&wprojr_p, g_wprojr);

    cudaFuncSetAttribute(gemm_h, cudaFuncAttributeMaxDynamicSharedMemorySize,
                         SMEM_GH);
    cudaFuncSetAttribute(gemm_bt, cudaFuncAttributeMaxDynamicSharedMemorySize,
                         SMEM_GT);
    cudaFuncSetAttribute(attn_kernel, cudaFuncAttributeMaxDynamicSharedMemorySize,
                         SMEM_ATT);

    // 0) operand converts: fp16 for GEMM1, tf32 for GEMM2 weights
    int n4x = MROWS * DIMC / 4;
    f2h_k<<<(n4x + 255) / 256, 256>>>((const float4*)x, (__half2*)xh_p, n4x);
    int n4wq = 3 * DIMC * DIMC / 4;
    f2h_k<<<(n4wq + 255) / 256, 256>>>((const float4*)w_qkv, (__half2*)wqkvh_p, n4wq);
    int n4wp = DIMC * DIMC / 4;
    round_tf32_k<<<(n4wp + 255) / 256, 256>>>(w_proj, wprojr_p, n4wp);

    // 1) QKV projection (fp16 tensor): [33280,1024] x [3072,1024]^T
    gemm_h<<<dim3(3 * DIMC / 128, MROWS / 128), 256, SMEM_GH>>>(
        xh_p, wqkvh_p, qkv_p, MROWS, 3 * DIMC, DIMC);
    // 2) Fused LN + attention per (b,h); emits tf32-rounded fp32
    attn_kernel<<<dim3(HEADS, BATCH), 256, SMEM_ATT>>>(
        qkv_p, bias, bscale, qn_w, qn_b, kn_w, kn_b, att_p);
    // 3) Output projection (tf32 tensor): [33280,1024] x [1024,1024]^T
    gemm_bt<<<dim3(DIMC / 128, MROWS / 128), 256, SMEM_GT>>>(
        att_p, wprojr_p, out, MROWS, DIMC, DIMC);
}

// round 12
// speedup vs baseline: 2.3035x; 1.0154x over previous
#include <cuda_runtime.h>
#include <cuda_fp16.h>
#include <cstdint>
#include <mma.h>
using namespace nvcuda;

#define DIMC   1024
#define HEADS  16
#define HD     64
#define BATCH  512
#define SEQ    65
#define MROWS  (BATCH * SEQ)   // 33280 = 260*128

// Scratch (allocation-free rule: __device__ globals)
__device__ float  g_qkv[(size_t)MROWS * 3 * DIMC];    // GEMM1 out (fp32)
__device__ float  g_att[(size_t)MROWS * DIMC];        // attn out (tf32-rounded)
__device__ __half g_xh[(size_t)MROWS * DIMC];         // x -> half
__device__ __half g_wqkvh[(size_t)3 * DIMC * DIMC];   // w_qkv -> half
__device__ float  g_wprojr[(size_t)DIMC * DIMC];      // w_proj -> tf32-rounded

// ---------------------------------------------------------------------------
// converts
// ---------------------------------------------------------------------------
__device__ __forceinline__ float tf32r(float x) {
    unsigned u;
    asm("cvt.rn.tf32.f32 %0, %1;" : "=r"(u) : "f"(x));
    return __uint_as_float(u);
}

__global__ void __launch_bounds__(256) f2h_k(const float4* __restrict__ in,
                                             __half2* __restrict__ out, int n4) {
    int i = blockIdx.x * blockDim.x + threadIdx.x;
    if (i < n4) {
        float4 v = in[i];
        out[2 * i]     = __floats2half2_rn(v.x, v.y);
        out[2 * i + 1] = __floats2half2_rn(v.z, v.w);
    }
}

__global__ void __launch_bounds__(256) round_tf32_k(const float* __restrict__ in,
                                                    float* __restrict__ out, int n4) {
    int i = blockIdx.x * blockDim.x + threadIdx.x;
    if (i < n4) {
        float4 v = ((const float4*)in)[i];
        v.x = tf32r(v.x); v.y = tf32r(v.y); v.z = tf32r(v.z); v.w = tf32r(v.w);
        ((float4*)out)[i] = v;
    }
}

__device__ __forceinline__ void cp_async16(void* smem, const void* gmem) {
    unsigned s = (unsigned)__cvta_generic_to_shared(smem);
    asm volatile("cp.async.cg.shared.global [%0], [%1], 16;\n" ::"r"(s), "l"(gmem));
}

// ---------------------------------------------------------------------------
// GEMM1: fp16 WMMA m16n16k16, fp32 acc. C = A[M,K] * B[N,K]^T.
// CTA 128x128, 8 warps (4Mx2N), warp tile 32x64 (2x4 frags).
// 3-stage cp.async ring, ONE __syncthreads per iter. 2 CTAs/SM.
// ---------------------------------------------------------------------------
constexpr int TKH  = 64;             // K halfs per stage
constexpr int LDTH = 72;             // padded leading dim (halfs, 144B)
constexpr int STGH = 256 * LDTH;     // halfs/stage: A 128 + B 128 rows
#define SMEM_GH (3 * STGH * 2)       // 110592 bytes

__global__ void __launch_bounds__(256, 2) gemm_h(const __half* __restrict__ A,
                                                 const __half* __restrict__ B,
                                                 float* __restrict__ C,
                                                 int M, int N, int K) {
    extern __shared__ __align__(16) __half smh[];
    const int tid  = threadIdx.x;
    const int warp = tid >> 5;
    const int wm   = warp >> 1, wn = warp & 1;   // 4 x 2
    const int bm   = blockIdx.y * 128, bn = blockIdx.x * 128;

    wmma::fragment<wmma::accumulator, 16, 16, 16, float> acc[2][4];
#pragma unroll
    for (int i = 0; i < 2; i++)
#pragma unroll
        for (int j = 0; j < 4; j++) wmma::fill_fragment(acc[i][j], 0.0f);

    const int lrow = tid >> 3;          // 0..31
    const int lcol = (tid & 7) << 3;    // 0..56 halfs (16B chunks)

    auto load_stage = [&](int s, int k0) {
        __half* As = smh + s * STGH;
        __half* Bs = As + 128 * LDTH;
#pragma unroll
        for (int t = 0; t < 4; t++) {
            int r = lrow + t * 32;
            cp_async16(&As[r * LDTH + lcol], &A[(size_t)(bm + r) * K + k0 + lcol]);
        }
#pragma unroll
        for (int t = 0; t < 4; t++) {
            int r = lrow + t * 32;
            cp_async16(&Bs[r * LDTH + lcol], &B[(size_t)(bn + r) * K + k0 + lcol]);
        }
        asm volatile("cp.async.commit_group;\n" ::: "memory");
    };

    load_stage(0, 0);
    load_stage(1, TKH);

    const int niter = K / TKH;   // 16
    for (int j = 0; j < niter; j++) {
        // stage j ready when at most 1 newer group pending
        asm volatile("cp.async.wait_group 1;\n" ::: "memory");
        __syncthreads();
        // prefetch j+2 into slot (j+2)%3 — consumed last at iter j-1, safe
        if (j + 2 < niter) load_stage((j + 2) % 3, (j + 2) * TKH);

        const __half* As = smh + (j % 3) * STGH;
        const __half* Bs = As + 128 * LDTH;
#pragma unroll
        for (int kk = 0; kk < TKH; kk += 16) {
            wmma::fragment<wmma::matrix_a, 16, 16, 16, __half, wmma::row_major> af[2];
            wmma::fragment<wmma::matrix_b, 16, 16, 16, __half, wmma::col_major> bf[4];
#pragma unroll
            for (int i = 0; i < 2; i++)
                wmma::load_matrix_sync(af[i], &As[(wm * 32 + i * 16) * LDTH + kk], LDTH);
#pragma unroll
            for (int jj = 0; jj < 4; jj++)
                wmma::load_matrix_sync(bf[jj], &Bs[(wn * 64 + jj * 16) * LDTH + kk], LDTH);
#pragma unroll
            for (int i = 0; i < 2; i++)
#pragma unroll
                for (int jj = 0; jj < 4; jj++)
                    wmma::mma_sync(acc[i][jj], af[i], bf[jj], acc[i][jj]);
        }
    }

#pragma unroll
    for (int i = 0; i < 2; i++)
#pragma unroll
        for (int j = 0; j < 4; j++)
            wmma::store_matrix_sync(
                &C[(size_t)(bm + wm * 32 + i * 16) * N + bn + wn * 64 + j * 16],
                acc[i][j], N, wmma::mem_row_major);
}

// ---------------------------------------------------------------------------
// GEMM2: tf32 WMMA (pre-rounded inputs), fp32 acc.
// CTA 128x128, 8 warps, warp tile 32x64. 3-stage ring, one sync/iter.
// ---------------------------------------------------------------------------
constexpr int TKF  = 32;
constexpr int LDTF = 36;             // 144B rows
constexpr int STGF = 256 * LDTF;
#define SMEM_GT (3 * STGF * 4)       // 110592 bytes

__global__ void __launch_bounds__(256, 2) gemm_bt(const float* __restrict__ A,
                                                  const float* __restrict__ B,
                                                  float* __restrict__ C,
                                                  int M, int N, int K) {
    extern __shared__ __align__(16) float smf2[];
    const int tid  = threadIdx.x;
    const int warp = tid >> 5;
    const int wm   = warp >> 1, wn = warp & 1;
    const int bm   = blockIdx.y * 128, bn = blockIdx.x * 128;

    wmma::fragment<wmma::accumulator, 16, 16, 8, float> acc[2][4];
#pragma unroll
    for (int i = 0; i < 2; i++)
#pragma unroll
        for (int j = 0; j < 4; j++) wmma::fill_fragment(acc[i][j], 0.0f);

    const int lrow = tid >> 3;
    const int lcol = (tid & 7) << 2;    // floats (16B chunks)

    auto load_stage = [&](int s, int k0) {
        float* As = smf2 + s * STGF;
        float* Bs = As + 128 * LDTF;
#pragma unroll
        for (int t = 0; t < 4; t++) {
            int r = lrow + t * 32;
            cp_async16(&As[r * LDTF + lcol], &A[(size_t)(bm + r) * K + k0 + lcol]);
        }
#pragma unroll
        for (int t = 0; t < 4; t++) {
            int r = lrow + t * 32;
            cp_async16(&Bs[r * LDTF + lcol], &B[(size_t)(bn + r) * K + k0 + lcol]);
        }
        asm volatile("cp.async.commit_group;\n" ::: "memory");
    };

    load_stage(0, 0);
    load_stage(1, TKF);

    const int niter = K / TKF;   // 32
    for (int j = 0; j < niter; j++) {
        asm volatile("cp.async.wait_group 1;\n" ::: "memory");
        __syncthreads();
        if (j + 2 < niter) load_stage((j + 2) % 3, (j + 2) * TKF);

        const float* As = smf2 + (j % 3) * STGF;
        const float* Bs = As + 128 * LDTF;
#pragma unroll
        for (int kk = 0; kk < TKF; kk += 8) {
            wmma::fragment<wmma::matrix_a, 16, 16, 8, wmma::precision::tf32,
                           wmma::row_major> af[2];
            wmma::fragment<wmma::matrix_b, 16, 16, 8, wmma::precision::tf32,
                           wmma::col_major> bf[4];
#pragma unroll
            for (int i = 0; i < 2; i++)
                wmma::load_matrix_sync(af[i], &As[(wm * 32 + i * 16) * LDTF + kk], LDTF);
#pragma unroll
            for (int jj = 0; jj < 4; jj++)
                wmma::load_matrix_sync(bf[jj], &Bs[(wn * 64 + jj * 16) * LDTF + kk], LDTF);
#pragma unroll
            for (int i = 0; i < 2; i++)
#pragma unroll
                for (int jj = 0; jj < 4; jj++)
                    wmma::mma_sync(acc[i][jj], af[i], bf[jj], acc[i][jj]);
        }
    }

#pragma unroll
    for (int i = 0; i < 2; i++)
#pragma unroll
        for (int j = 0; j < 4; j++)
            wmma::store_matrix_sync(
                &C[(size_t)(bm + wm * 32 + i * 16) * N + bn + wn * 64 + j * 16],
                acc[i][j], N, wmma::mem_row_major);
}

// ---------------------------------------------------------------------------
// Fused attention (unchanged): LN, QK^T+bias, softmax, PV.
// Epilogue rounds to tf32 (feeds tf32 GEMM2).
// ---------------------------------------------------------------------------
#define Q_OFF  0
#define KV_OFF 4624
#define S_OFF  9248
#define SMEM_ATT (13872 * 4)  // 55488 bytes

__global__ void __launch_bounds__(256) attn_kernel(
    const float* __restrict__ qkv, const float* __restrict__ bias,
    const float* __restrict__ bscale_p,
    const float* __restrict__ qn_w, const float* __restrict__ qn_b,
    const float* __restrict__ kn_w, const float* __restrict__ kn_b,
    float* __restrict__ outp) {
    extern __shared__ float smf[];
    float* q_s  = smf + Q_OFF;
    float* kv_s = smf + KV_OFF;
    float* s_s  = smf + S_OFF;

    const int tid = threadIdx.x, lane = tid & 31, warp = tid >> 5;
    const int h = blockIdx.x, b = blockIdx.y;
    const float bscale = *bscale_p;
    const size_t base = (size_t)b * SEQ * 3072 + (size_t)h * 64;

    for (int i = tid; i < 68 * 64; i += 256) {
        int n = i >> 6, d = i & 63;
        float qv = 0.f, kv = 0.f;
        if (n < SEQ) {
            qv = qkv[base + (size_t)n * 3072 + d];
            kv = qkv[base + (size_t)n * 3072 + 1024 + d];
        }
        q_s[n * 68 + d]  = qv;
        kv_s[d * 68 + n] = kv;
    }
    __syncthreads();

    const float qw0 = qn_w[lane], qw1 = qn_w[lane + 32];
    const float qb0 = qn_b[lane], qb1 = qn_b[lane + 32];
    const float kw0 = kn_w[lane], kw1 = kn_w[lane + 32];
    const float kb0 = kn_b[lane], kb1 = kn_b[lane + 32];
    for (int n = warp; n < SEQ; n += 8) {
        float x0 = q_s[n * 68 + lane], x1 = q_s[n * 68 + lane + 32];
        float s = x0 + x1, sq = x0 * x0 + x1 * x1;
#pragma unroll
        for (int o = 16; o; o >>= 1) {
            s += __shfl_xor_sync(0xffffffffu, s, o);
            sq += __shfl_xor_sync(0xffffffffu, sq, o);
        }
        float mu = s * (1.f / 64.f);
        float rstd = rsqrtf(sq * (1.f / 64.f) - mu * mu + 1e-5f);
        q_s[n * 68 + lane]      = ((x0 - mu) * rstd * qw0 + qb0) * 0.125f;
        q_s[n * 68 + lane + 32] = ((x1 - mu) * rstd * qw1 + qb1) * 0.125f;

        x0 = kv_s[lane * 68 + n]; x1 = kv_s[(lane + 32) * 68 + n];
        s = x0 + x1; sq = x0 * x0 + x1 * x1;
#pragma unroll
        for (int o = 16; o; o >>= 1) {
            s += __shfl_xor_sync(0xffffffffu, s, o);
            sq += __shfl_xor_sync(0xffffffffu, sq, o);
        }
        mu = s * (1.f / 64.f);
        rstd = rsqrtf(sq * (1.f / 64.f) - mu * mu + 1e-5f);
        kv_s[lane * 68 + n]        = (x0 - mu) * rstd * kw0 + kb0;
        kv_s[(lane + 32) * 68 + n] = (x1 - mu) * rstd * kw1 + kb1;
    }
    __syncthreads();

    for (int idx = tid; idx < 17 * 17; idx += 256) {
        int n0 = (idx / 17) * 4, m0 = (idx % 17) * 4;
        float acc[4][4] = {};
#pragma unroll 8
        for (int d = 0; d < 64; d++) {
            float4 kv4 = *(float4*)&kv_s[d * 68 + m0];
            float kvv[4] = {kv4.x, kv4.y, kv4.z, kv4.w};
#pragma unroll
            for (int i = 0; i < 4; i++) {
                float qv = q_s[(n0 + i) * 68 + d];
#pragma unroll
                for (int j = 0; j < 4; j++) acc[i][j] = fmaf(qv, kvv[j], acc[i][j]);
            }
        }
#pragma unroll
        for (int i = 0; i < 4; i++)
#pragma unroll
            for (int j = 0; j < 4; j++) {
                int n = n0 + i, m = m0 + j;
                float bv = (n < SEQ && m < SEQ)
                               ? bias[((size_t)h * SEQ + n) * SEQ + m] * bscale
                               : 0.f;
                s_s[n * 68 + m] = acc[i][j] + bv;
            }
    }
    __syncthreads();

    for (int i = tid; i < 68 * 64; i += 256) {
        int n = i >> 6, d = i & 63;
        kv_s[n * 68 + d] =
            (n < SEQ) ? qkv[base + (size_t)n * 3072 + 2048 + d] : 0.f;
    }
    for (int n = warp; n < SEQ; n += 8) {
        float v0 = s_s[n * 68 + lane], v1 = s_s[n * 68 + lane + 32];
        float v2 = (lane == 0) ? s_s[n * 68 + 64] : -3.4e38f;
        float mx = fmaxf(fmaxf(v0, v1), v2);
#pragma unroll
        for (int o = 16; o; o >>= 1) mx = fmaxf(mx, __shfl_xor_sync(0xffffffffu, mx, o));
        float e0 = __expf(v0 - mx), e1 = __expf(v1 - mx);
        float e2 = (lane == 0) ? __expf(v2 - mx) : 0.f;
        float sum = e0 + e1 + e2;
#pragma unroll
        for (int o = 16; o; o >>= 1) sum += __shfl_xor_sync(0xffffffffu, sum, o);
        float inv = 1.f / sum;
        s_s[n * 68 + lane]      = e0 * inv;
        s_s[n * 68 + lane + 32] = e1 * inv;
        if (lane == 0) {
            s_s[n * 68 + 64] = e2 * inv;
            s_s[n * 68 + 65] = 0.f; s_s[n * 68 + 66] = 0.f; s_s[n * 68 + 67] = 0.f;
        }
    }
    __syncthreads();

    for (int idx = tid; idx < 17 * 16; idx += 256) {
        int n0 = (idx / 16) * 4, d0 = (idx % 16) * 4;
        float acc[4][4] = {};
#pragma unroll 4
        for (int m = 0; m < 68; m++) {
            float4 vv4 = *(float4*)&kv_s[m * 68 + d0];
            float vvv[4] = {vv4.x, vv4.y, vv4.z, vv4.w};
#pragma unroll
            for (int i = 0; i < 4; i++) {
                float pv = s_s[(n0 + i) * 68 + m];
#pragma unroll
                for (int j = 0; j < 4; j++) acc[i][j] = fmaf(pv, vvv[j], acc[i][j]);
            }
        }
#pragma unroll
        for (int i = 0; i < 4; i++) {
            int n = n0 + i;
            if (n < SEQ) {
                size_t o = ((size_t)b * SEQ + n) * DIMC + (size_t)h * 64 + d0;
#pragma unroll
                for (int j = 0; j < 4; j++) outp[o + j] = tf32r(acc[i][j]);
            }
        }
    }
}

// ---------------------------------------------------------------------------
extern "C" void kernel_launch(void* const* d_in, const int* in_sizes, int n_in,
                              void* d_out, int out_size) {
    const float* x      = (const float*)d_in[0];
    const float* w_qkv  = (const float*)d_in[1];
    const float* w_proj = (const float*)d_in[2];
    const float* qn_w   = (const float*)d_in[3];
    const float* qn_b   = (const float*)d_in[4];
    const float* kn_w   = (const float*)d_in[5];
    const float* kn_b   = (const float*)d_in[6];
    const float* bias   = (const float*)d_in[7];
    const float* bscale = (const float*)d_in[8];
    float* out          = (float*)d_out;

    float *qkv_p, *att_p, *wprojr_p;
    __half *xh_p, *wqkvh_p;
    cudaGetSymbolAddress((void**)&qkv_p, g_qkv);
    cudaGetSymbolAddress((void**)&att_p, g_att);
    cudaGetSymbolAddress((void**)&xh_p, g_xh);
    cudaGetSymbolAddress((void**)&wqkvh_p, g_wqkvh);
    cudaGetSymbolAddress((void**)&wprojr_p, g_wprojr);

    cudaFuncSetAttribute(gemm_h, cudaFuncAttributeMaxDynamicSharedMemorySize,
                         SMEM_GH);
    cudaFuncSetAttribute(gemm_bt, cudaFuncAttributeMaxDynamicSharedMemorySize,
                         SMEM_GT);
    cudaFuncSetAttribute(attn_kernel, cudaFuncAttributeMaxDynamicSharedMemorySize,
                         SMEM_ATT);

    // 0) operand converts: fp16 for GEMM1, tf32 for GEMM2 weights
    int n4x = MROWS * DIMC / 4;
    f2h_k<<<(n4x + 255) / 256, 256>>>((const float4*)x, (__half2*)xh_p, n4x);
    int n4wq = 3 * DIMC * DIMC / 4;
    f2h_k<<<(n4wq + 255) / 256, 256>>>((const float4*)w_qkv, (__half2*)wqkvh_p, n4wq);
    int n4wp = DIMC * DIMC / 4;
    round_tf32_k<<<(n4wp + 255) / 256, 256>>>(w_proj, wprojr_p, n4wp);

    // 1) QKV projection (fp16 tensor): [33280,1024] x [3072,1024]^T
    gemm_h<<<dim3(3 * DIMC / 128, MROWS / 128), 256, SMEM_GH>>>(
        xh_p, wqkvh_p, qkv_p, MROWS, 3 * DIMC, DIMC);
    // 2) Fused LN + attention per (b,h); emits tf32-rounded fp32
    attn_kernel<<<dim3(HEADS, BATCH), 256, SMEM_ATT>>>(
        qkv_p, bias, bscale, qn_w, qn_b, kn_w, kn_b, att_p);
    // 3) Output projection (tf32 tensor): [33280,1024] x [1024,1024]^T
    gemm_bt<<<dim3(DIMC / 128, MROWS / 128), 256, SMEM_GT>>>(
        att_p, wprojr_p, out, MROWS, DIMC, DIMC);
}

// round 13
// speedup vs baseline: 2.3505x; 1.0204x over previous
#include <cuda_runtime.h>
#include <cuda_fp16.h>
#include <cstdint>
#include <mma.h>
using namespace nvcuda;

#define DIMC   1024
#define HEADS  16
#define HD     64
#define BATCH  512
#define SEQ    65
#define MROWS  (BATCH * SEQ)   // 33280 = 260*128

// Scratch (allocation-free rule: __device__ globals)
__device__ float  g_qkv[(size_t)MROWS * 3 * DIMC];    // GEMM1 out (fp32)
__device__ float  g_att[(size_t)MROWS * DIMC];        // attn out (tf32-rounded)
__device__ __half g_xh[(size_t)MROWS * DIMC];         // x -> half
__device__ __half g_wqkvh[(size_t)3 * DIMC * DIMC];   // w_qkv -> half
__device__ float  g_wprojr[(size_t)DIMC * DIMC];      // w_proj -> tf32-rounded

// ---------------------------------------------------------------------------
// converts
// ---------------------------------------------------------------------------
__device__ __forceinline__ float tf32r(float x) {
    unsigned u;
    asm("cvt.rn.tf32.f32 %0, %1;" : "=r"(u) : "f"(x));
    return __uint_as_float(u);
}

__global__ void __launch_bounds__(256) f2h_k(const float4* __restrict__ in,
                                             __half2* __restrict__ out, int n4) {
    int i = blockIdx.x * blockDim.x + threadIdx.x;
    if (i < n4) {
        float4 v = in[i];
        out[2 * i]     = __floats2half2_rn(v.x, v.y);
        out[2 * i + 1] = __floats2half2_rn(v.z, v.w);
    }
}

__global__ void __launch_bounds__(256) round_tf32_k(const float* __restrict__ in,
                                                    float* __restrict__ out, int n4) {
    int i = blockIdx.x * blockDim.x + threadIdx.x;
    if (i < n4) {
        float4 v = ((const float4*)in)[i];
        v.x = tf32r(v.x); v.y = tf32r(v.y); v.z = tf32r(v.z); v.w = tf32r(v.w);
        ((float4*)out)[i] = v;
    }
}

__device__ __forceinline__ void cp_async16(void* smem, const void* gmem) {
    unsigned s = (unsigned)__cvta_generic_to_shared(smem);
    asm volatile("cp.async.cg.shared.global [%0], [%1], 16;\n" ::"r"(s), "l"(gmem));
}

// ---------------------------------------------------------------------------
// GEMM1: fp16 WMMA m16n16k16, fp32 acc. C = A[M,K] * B[N,K]^T.
// CTA 128x128, 8 warps (4Mx2N), warp tile 32x64. 3-stage cp.async ring.
// ---------------------------------------------------------------------------
constexpr int TKH  = 64;
constexpr int LDTH = 72;
constexpr int STGH = 256 * LDTH;
#define SMEM_GH (3 * STGH * 2)       // 110592 bytes

__global__ void __launch_bounds__(256, 2) gemm_h(const __half* __restrict__ A,
                                                 const __half* __restrict__ B,
                                                 float* __restrict__ C,
                                                 int M, int N, int K) {
    extern __shared__ __align__(16) __half smh[];
    const int tid  = threadIdx.x;
    const int warp = tid >> 5;
    const int wm   = warp >> 1, wn = warp & 1;
    const int bm   = blockIdx.y * 128, bn = blockIdx.x * 128;

    wmma::fragment<wmma::accumulator, 16, 16, 16, float> acc[2][4];
#pragma unroll
    for (int i = 0; i < 2; i++)
#pragma unroll
        for (int j = 0; j < 4; j++) wmma::fill_fragment(acc[i][j], 0.0f);

    const int lrow = tid >> 3;
    const int lcol = (tid & 7) << 3;

    auto load_stage = [&](int s, int k0) {
        __half* As = smh + s * STGH;
        __half* Bs = As + 128 * LDTH;
#pragma unroll
        for (int t = 0; t < 4; t++) {
            int r = lrow + t * 32;
            cp_async16(&As[r * LDTH + lcol], &A[(size_t)(bm + r) * K + k0 + lcol]);
        }
#pragma unroll
        for (int t = 0; t < 4; t++) {
            int r = lrow + t * 32;
            cp_async16(&Bs[r * LDTH + lcol], &B[(size_t)(bn + r) * K + k0 + lcol]);
        }
        asm volatile("cp.async.commit_group;\n" ::: "memory");
    };

    load_stage(0, 0);
    load_stage(1, TKH);

    const int niter = K / TKH;   // 16
    for (int j = 0; j < niter; j++) {
        asm volatile("cp.async.wait_group 1;\n" ::: "memory");
        __syncthreads();
        if (j + 2 < niter) load_stage((j + 2) % 3, (j + 2) * TKH);

        const __half* As = smh + (j % 3) * STGH;
        const __half* Bs = As + 128 * LDTH;
#pragma unroll
        for (int kk = 0; kk < TKH; kk += 16) {
            wmma::fragment<wmma::matrix_a, 16, 16, 16, __half, wmma::row_major> af[2];
            wmma::fragment<wmma::matrix_b, 16, 16, 16, __half, wmma::col_major> bf[4];
#pragma unroll
            for (int i = 0; i < 2; i++)
                wmma::load_matrix_sync(af[i], &As[(wm * 32 + i * 16) * LDTH + kk], LDTH);
#pragma unroll
            for (int jj = 0; jj < 4; jj++)
                wmma::load_matrix_sync(bf[jj], &Bs[(wn * 64 + jj * 16) * LDTH + kk], LDTH);
#pragma unroll
            for (int i = 0; i < 2; i++)
#pragma unroll
                for (int jj = 0; jj < 4; jj++)
                    wmma::mma_sync(acc[i][jj], af[i], bf[jj], acc[i][jj]);
        }
    }

#pragma unroll
    for (int i = 0; i < 2; i++)
#pragma unroll
        for (int j = 0; j < 4; j++)
            wmma::store_matrix_sync(
                &C[(size_t)(bm + wm * 32 + i * 16) * N + bn + wn * 64 + j * 16],
                acc[i][j], N, wmma::mem_row_major);
}

// ---------------------------------------------------------------------------
// GEMM2: tf32 WMMA (pre-rounded inputs), fp32 acc.
// CTA 128x128, 8 warps, warp tile 32x64. 3-stage ring.
// ---------------------------------------------------------------------------
constexpr int TKF  = 32;
constexpr int LDTF = 36;
constexpr int STGF = 256 * LDTF;
#define SMEM_GT (3 * STGF * 4)       // 110592 bytes

__global__ void __launch_bounds__(256, 2) gemm_bt(const float* __restrict__ A,
                                                  const float* __restrict__ B,
                                                  float* __restrict__ C,
                                                  int M, int N, int K) {
    extern __shared__ __align__(16) float smf2[];
    const int tid  = threadIdx.x;
    const int warp = tid >> 5;
    const int wm   = warp >> 1, wn = warp & 1;
    const int bm   = blockIdx.y * 128, bn = blockIdx.x * 128;

    wmma::fragment<wmma::accumulator, 16, 16, 8, float> acc[2][4];
#pragma unroll
    for (int i = 0; i < 2; i++)
#pragma unroll
        for (int j = 0; j < 4; j++) wmma::fill_fragment(acc[i][j], 0.0f);

    const int lrow = tid >> 3;
    const int lcol = (tid & 7) << 2;

    auto load_stage = [&](int s, int k0) {
        float* As = smf2 + s * STGF;
        float* Bs = As + 128 * LDTF;
#pragma unroll
        for (int t = 0; t < 4; t++) {
            int r = lrow + t * 32;
            cp_async16(&As[r * LDTF + lcol], &A[(size_t)(bm + r) * K + k0 + lcol]);
        }
#pragma unroll
        for (int t = 0; t < 4; t++) {
            int r = lrow + t * 32;
            cp_async16(&Bs[r * LDTF + lcol], &B[(size_t)(bn + r) * K + k0 + lcol]);
        }
        asm volatile("cp.async.commit_group;\n" ::: "memory");
    };

    load_stage(0, 0);
    load_stage(1, TKF);

    const int niter = K / TKF;   // 32
    for (int j = 0; j < niter; j++) {
        asm volatile("cp.async.wait_group 1;\n" ::: "memory");
        __syncthreads();
        if (j + 2 < niter) load_stage((j + 2) % 3, (j + 2) * TKF);

        const float* As = smf2 + (j % 3) * STGF;
        const float* Bs = As + 128 * LDTF;
#pragma unroll
        for (int kk = 0; kk < TKF; kk += 8) {
            wmma::fragment<wmma::matrix_a, 16, 16, 8, wmma::precision::tf32,
                           wmma::row_major> af[2];
            wmma::fragment<wmma::matrix_b, 16, 16, 8, wmma::precision::tf32,
                           wmma::col_major> bf[4];
#pragma unroll
            for (int i = 0; i < 2; i++)
                wmma::load_matrix_sync(af[i], &As[(wm * 32 + i * 16) * LDTF + kk], LDTF);
#pragma unroll
            for (int jj = 0; jj < 4; jj++)
                wmma::load_matrix_sync(bf[jj], &Bs[(wn * 64 + jj * 16) * LDTF + kk], LDTF);
#pragma unroll
            for (int i = 0; i < 2; i++)
#pragma unroll
                for (int jj = 0; jj < 4; jj++)
                    wmma::mma_sync(acc[i][jj], af[i], bf[jj], acc[i][jj]);
        }
    }

#pragma unroll
    for (int i = 0; i < 2; i++)
#pragma unroll
        for (int j = 0; j < 4; j++)
            wmma::store_matrix_sync(
                &C[(size_t)(bm + wm * 32 + i * 16) * N + bn + wn * 64 + j * 16],
                acc[i][j], N, wmma::mem_row_major);
}

// ---------------------------------------------------------------------------
// Fused attention v2: one CTA per (b, h).
//  - LN fused with gmem load (fp32), Q/K written as HALF
//  - S = Q K^T on fp16 tensor cores (80x80 padded, k=64), fp32 acc
//  - bias folded into fp32 softmax read; softmax fp32
//  - O = P V scalar fp32 (no new direct-path error); epilogue tf32-rounds
// ---------------------------------------------------------------------------
#define LDQH  72                       // half leading dim (144B rows)
#define LDS2  84                       // fp32 S leading dim
#define ATT_QH 0
#define ATT_KH (80 * LDQH * 2)                  // 11520
#define ATT_S  (2 * 80 * LDQH * 2)              // 23040
#define ATT_V  (ATT_S + 80 * LDS2 * 4)          // 49920
#define SMEM_ATT2 (ATT_V + 68 * 68 * 4)         // 68416 bytes

__global__ void __launch_bounds__(256) attn_kernel(
    const float* __restrict__ qkv, const float* __restrict__ bias,
    const float* __restrict__ bscale_p,
    const float* __restrict__ qn_w, const float* __restrict__ qn_b,
    const float* __restrict__ kn_w, const float* __restrict__ kn_b,
    float* __restrict__ outp) {
    extern __shared__ __align__(16) char smc[];
    __half* qh  = (__half*)(smc + ATT_QH);
    __half* kh  = (__half*)(smc + ATT_KH);
    float*  s_s = (float*)(smc + ATT_S);
    float*  v_s = (float*)(smc + ATT_V);

    const int tid = threadIdx.x, lane = tid & 31, warp = tid >> 5;
    const int h = blockIdx.x, b = blockIdx.y;
    const float bscale = *bscale_p;
    const size_t base = (size_t)b * SEQ * 3072 + (size_t)h * 64;

    // zero pad rows 65..79 of qh & kh (36 uint32 words per row)
    for (int i = tid; i < 15 * 36 * 2; i += 256) {
        int arr = i / (15 * 36);
        int rem = i % (15 * 36);
        int r = 65 + rem / 36, c = rem % 36;
        ((unsigned*)(arr ? kh : qh))[r * 36 + c] = 0u;
    }

    // fused gmem load + LayerNorm -> half (q scaled by hd^-0.5)
    const float qw0 = qn_w[lane], qw1 = qn_w[lane + 32];
    const float qb0 = qn_b[lane], qb1 = qn_b[lane + 32];
    const float kw0 = kn_w[lane], kw1 = kn_w[lane + 32];
    const float kb0 = kn_b[lane], kb1 = kn_b[lane + 32];
    for (int n = warp; n < SEQ; n += 8) {
        float x0 = qkv[base + (size_t)n * 3072 + lane];
        float x1 = qkv[base + (size_t)n * 3072 + lane + 32];
        float s = x0 + x1, sq = x0 * x0 + x1 * x1;
#pragma unroll
        for (int o = 16; o; o >>= 1) {
            s += __shfl_xor_sync(0xffffffffu, s, o);
            sq += __shfl_xor_sync(0xffffffffu, sq, o);
        }
        float mu = s * (1.f / 64.f);
        float rstd = rsqrtf(sq * (1.f / 64.f) - mu * mu + 1e-5f);
        qh[n * LDQH + lane]      = __float2half(((x0 - mu) * rstd * qw0 + qb0) * 0.125f);
        qh[n * LDQH + lane + 32] = __float2half(((x1 - mu) * rstd * qw1 + qb1) * 0.125f);

        x0 = qkv[base + (size_t)n * 3072 + 1024 + lane];
        x1 = qkv[base + (size_t)n * 3072 + 1024 + lane + 32];
        s = x0 + x1; sq = x0 * x0 + x1 * x1;
#pragma unroll
        for (int o = 16; o; o >>= 1) {
            s += __shfl_xor_sync(0xffffffffu, s, o);
            sq += __shfl_xor_sync(0xffffffffu, sq, o);
        }
        mu = s * (1.f / 64.f);
        rstd = rsqrtf(sq * (1.f / 64.f) - mu * mu + 1e-5f);
        kh[n * LDQH + lane]      = __float2half((x0 - mu) * rstd * kw0 + kb0);
        kh[n * LDQH + lane + 32] = __float2half((x1 - mu) * rstd * kw1 + kb1);
    }
    __syncthreads();

    // S = Q K^T on tensor cores (warps 0-4, 16-row strips); warps 5-7 load V
    if (warp < 5) {
        wmma::fragment<wmma::accumulator, 16, 16, 16, float> sacc[5];
#pragma unroll
        for (int m = 0; m < 5; m++) wmma::fill_fragment(sacc[m], 0.0f);
#pragma unroll
        for (int kk = 0; kk < 4; kk++) {
            wmma::fragment<wmma::matrix_a, 16, 16, 16, __half, wmma::row_major> aq;
            wmma::load_matrix_sync(aq, &qh[warp * 16 * LDQH + kk * 16], LDQH);
#pragma unroll
            for (int m = 0; m < 5; m++) {
                wmma::fragment<wmma::matrix_b, 16, 16, 16, __half, wmma::col_major> bk;
                wmma::load_matrix_sync(bk, &kh[m * 16 * LDQH + kk * 16], LDQH);
                wmma::mma_sync(sacc[m], aq, bk, sacc[m]);
            }
        }
#pragma unroll
        for (int m = 0; m < 5; m++)
            wmma::store_matrix_sync(&s_s[warp * 16 * LDS2 + m * 16], sacc[m],
                                    LDS2, wmma::mem_row_major);
    } else {
        for (int i = tid - 160; i < 68 * 64; i += 96) {
            int n = i >> 6, d = i & 63;
            v_s[n * 68 + d] =
                (n < SEQ) ? qkv[base + (size_t)n * 3072 + 2048 + d] : 0.f;
        }
    }
    __syncthreads();

    // softmax rows (fp32), bias folded into the read
    for (int n = warp; n < SEQ; n += 8) {
        const float* brow = &bias[((size_t)h * SEQ + n) * SEQ];
        float v0 = s_s[n * LDS2 + lane]      + brow[lane] * bscale;
        float v1 = s_s[n * LDS2 + lane + 32] + brow[lane + 32] * bscale;
        float v2 = (lane == 0) ? s_s[n * LDS2 + 64] + brow[64] * bscale : -3.4e38f;
        float mx = fmaxf(fmaxf(v0, v1), v2);
#pragma unroll
        for (int o = 16; o; o >>= 1) mx = fmaxf(mx, __shfl_xor_sync(0xffffffffu, mx, o));
        float e0 = __expf(v0 - mx), e1 = __expf(v1 - mx);
        float e2 = (lane == 0) ? __expf(v2 - mx) : 0.f;
        float sum = e0 + e1 + e2;
#pragma unroll
        for (int o = 16; o; o >>= 1) sum += __shfl_xor_sync(0xffffffffu, sum, o);
        float inv = 1.f / sum;
        s_s[n * LDS2 + lane]      = e0 * inv;
        s_s[n * LDS2 + lane + 32] = e1 * inv;
        if (lane == 0) {
            s_s[n * LDS2 + 64] = e2 * inv;
            s_s[n * LDS2 + 65] = 0.f; s_s[n * LDS2 + 66] = 0.f; s_s[n * LDS2 + 67] = 0.f;
        }
    }
    __syncthreads();

    // O = P V (scalar fp32, 4x4 register tiles); epilogue rounds to tf32
    for (int idx = tid; idx < 17 * 16; idx += 256) {
        int n0 = (idx / 16) * 4, d0 = (idx % 16) * 4;
        float acc[4][4] = {};
#pragma unroll 4
        for (int m = 0; m < 68; m++) {
            float4 vv4 = *(float4*)&v_s[m * 68 + d0];
            float vvv[4] = {vv4.x, vv4.y, vv4.z, vv4.w};
#pragma unroll
            for (int i = 0; i < 4; i++) {
                float pv = s_s[(n0 + i) * LDS2 + m];
#pragma unroll
                for (int j = 0; j < 4; j++) acc[i][j] = fmaf(pv, vvv[j], acc[i][j]);
            }
        }
#pragma unroll
        for (int i = 0; i < 4; i++) {
            int n = n0 + i;
            if (n < SEQ) {
                size_t o = ((size_t)b * SEQ + n) * DIMC + (size_t)h * 64 + d0;
#pragma unroll
                for (int j = 0; j < 4; j++) outp[o + j] = tf32r(acc[i][j]);
            }
        }
    }
}

// ---------------------------------------------------------------------------
extern "C" void kernel_launch(void* const* d_in, const int* in_sizes, int n_in,
                              void* d_out, int out_size) {
    const float* x      = (const float*)d_in[0];
    const float* w_qkv  = (const float*)d_in[1];
    const float* w_proj = (const float*)d_in[2];
    const float* qn_w   = (const float*)d_in[3];
    const float* qn_b   = (const float*)d_in[4];
    const float* kn_w   = (const float*)d_in[5];
    const float* kn_b   = (const float*)d_in[6];
    const float* bias   = (const float*)d_in[7];
    const float* bscale = (const float*)d_in[8];
    float* out          = (float*)d_out;

    float *qkv_p, *att_p, *wprojr_p;
    __half *xh_p, *wqkvh_p;
    cudaGetSymbolAddress((void**)&qkv_p, g_qkv);
    cudaGetSymbolAddress((void**)&att_p, g_att);
    cudaGetSymbolAddress((void**)&xh_p, g_xh);
    cudaGetSymbolAddress((void**)&wqkvh_p, g_wqkvh);
    cudaGetSymbolAddress((void**)&wprojr_p, g_wprojr);

    cudaFuncSetAttribute(gemm_h, cudaFuncAttributeMaxDynamicSharedMemorySize,
                         SMEM_GH);
    cudaFuncSetAttribute(gemm_bt, cudaFuncAttributeMaxDynamicSharedMemorySize,
                         SMEM_GT);
    cudaFuncSetAttribute(attn_kernel, cudaFuncAttributeMaxDynamicSharedMemorySize,
                         SMEM_ATT2);

    // 0) operand converts: fp16 for GEMM1, tf32 for GEMM2 weights
    int n4x = MROWS * DIMC / 4;
    f2h_k<<<(n4x + 255) / 256, 256>>>((const float4*)x, (__half2*)xh_p, n4x);
    int n4wq = 3 * DIMC * DIMC / 4;
    f2h_k<<<(n4wq + 255) / 256, 256>>>((const float4*)w_qkv, (__half2*)wqkvh_p, n4wq);
    int n4wp = DIMC * DIMC / 4;
    round_tf32_k<<<(n4wp + 255) / 256, 256>>>(w_proj, wprojr_p, n4wp);

    // 1) QKV projection (fp16 tensor): [33280,1024] x [3072,1024]^T
    gemm_h<<<dim3(3 * DIMC / 128, MROWS / 128), 256, SMEM_GH>>>(
        xh_p, wqkvh_p, qkv_p, MROWS, 3 * DIMC, DIMC);
    // 2) Fused LN + attention per (b,h); QK^T on tensor cores
    attn_kernel<<<dim3(HEADS, BATCH), 256, SMEM_ATT2>>>(
        qkv_p, bias, bscale, qn_w, qn_b, kn_w, kn_b, att_p);
    // 3) Output projection (tf32 tensor): [33280,1024] x [1024,1024]^T
    gemm_bt<<<dim3(DIMC / 128, MROWS / 128), 256, SMEM_GT>>>(
        att_p, wprojr_p, out, MROWS, DIMC, DIMC);
}

// round 14
// speedup vs baseline: 2.4475x; 1.0413x over previous
#include <cuda_runtime.h>
#include <cuda_fp16.h>
#include <cstdint>
#include <mma.h>
using namespace nvcuda;

#define DIMC   1024
#define HEADS  16
#define HD     64
#define BATCH  512
#define SEQ    65
#define MROWS  (BATCH * SEQ)   // 33280 = 260*128

// Scratch (allocation-free rule: __device__ globals)
__device__ float  g_qkv[(size_t)MROWS * 3 * DIMC];    // GEMM1 out (fp32)
__device__ float  g_att[(size_t)MROWS * DIMC];        // attn out (tf32-rounded)
__device__ __half g_xh[(size_t)MROWS * DIMC];         // x -> half
__device__ __half g_wqkvh[(size_t)3 * DIMC * DIMC];   // w_qkv -> half
__device__ float  g_wprojr[(size_t)DIMC * DIMC];      // w_proj -> tf32-rounded

// ---------------------------------------------------------------------------
// converts
// ---------------------------------------------------------------------------
__device__ __forceinline__ float tf32r(float x) {
    unsigned u;
    asm("cvt.rn.tf32.f32 %0, %1;" : "=r"(u) : "f"(x));
    return __uint_as_float(u);
}

__global__ void __launch_bounds__(256) f2h_k(const float4* __restrict__ in,
                                             __half2* __restrict__ out, int n4) {
    int i = blockIdx.x * blockDim.x + threadIdx.x;
    if (i < n4) {
        float4 v = in[i];
        out[2 * i]     = __floats2half2_rn(v.x, v.y);
        out[2 * i + 1] = __floats2half2_rn(v.z, v.w);
    }
}

__global__ void __launch_bounds__(256) round_tf32_k(const float* __restrict__ in,
                                                    float* __restrict__ out, int n4) {
    int i = blockIdx.x * blockDim.x + threadIdx.x;
    if (i < n4) {
        float4 v = ((const float4*)in)[i];
        v.x = tf32r(v.x); v.y = tf32r(v.y); v.z = tf32r(v.z); v.w = tf32r(v.w);
        ((float4*)out)[i] = v;
    }
}

__device__ __forceinline__ void cp_async16(void* smem, const void* gmem) {
    unsigned s = (unsigned)__cvta_generic_to_shared(smem);
    asm volatile("cp.async.cg.shared.global [%0], [%1], 16;\n" ::"r"(s), "l"(gmem));
}

// ---------------------------------------------------------------------------
// GEMM1: fp16 WMMA m16n16k16, fp32 acc. C = A[M,K] * B[N,K]^T.
// CTA 128x128, 8 warps (4Mx2N), warp tile 32x64. 3-stage cp.async ring.
// ---------------------------------------------------------------------------
constexpr int TKH  = 64;
constexpr int LDTH = 72;
constexpr int STGH = 256 * LDTH;
#define SMEM_GH (3 * STGH * 2)       // 110592 bytes

__global__ void __launch_bounds__(256, 2) gemm_h(const __half* __restrict__ A,
                                                 const __half* __restrict__ B,
                                                 float* __restrict__ C,
                                                 int M, int N, int K) {
    extern __shared__ __align__(16) __half smh[];
    const int tid  = threadIdx.x;
    const int warp = tid >> 5;
    const int wm   = warp >> 1, wn = warp & 1;
    const int bm   = blockIdx.y * 128, bn = blockIdx.x * 128;

    wmma::fragment<wmma::accumulator, 16, 16, 16, float> acc[2][4];
#pragma unroll
    for (int i = 0; i < 2; i++)
#pragma unroll
        for (int j = 0; j < 4; j++) wmma::fill_fragment(acc[i][j], 0.0f);

    const int lrow = tid >> 3;
    const int lcol = (tid & 7) << 3;

    auto load_stage = [&](int s, int k0) {
        __half* As = smh + s * STGH;
        __half* Bs = As + 128 * LDTH;
#pragma unroll
        for (int t = 0; t < 4; t++) {
            int r = lrow + t * 32;
            cp_async16(&As[r * LDTH + lcol], &A[(size_t)(bm + r) * K + k0 + lcol]);
        }
#pragma unroll
        for (int t = 0; t < 4; t++) {
            int r = lrow + t * 32;
            cp_async16(&Bs[r * LDTH + lcol], &B[(size_t)(bn + r) * K + k0 + lcol]);
        }
        asm volatile("cp.async.commit_group;\n" ::: "memory");
    };

    load_stage(0, 0);
    load_stage(1, TKH);

    const int niter = K / TKH;   // 16
    for (int j = 0; j < niter; j++) {
        asm volatile("cp.async.wait_group 1;\n" ::: "memory");
        __syncthreads();
        if (j + 2 < niter) load_stage((j + 2) % 3, (j + 2) * TKH);

        const __half* As = smh + (j % 3) * STGH;
        const __half* Bs = As + 128 * LDTH;
#pragma unroll
        for (int kk = 0; kk < TKH; kk += 16) {
            wmma::fragment<wmma::matrix_a, 16, 16, 16, __half, wmma::row_major> af[2];
            wmma::fragment<wmma::matrix_b, 16, 16, 16, __half, wmma::col_major> bf[4];
#pragma unroll
            for (int i = 0; i < 2; i++)
                wmma::load_matrix_sync(af[i], &As[(wm * 32 + i * 16) * LDTH + kk], LDTH);
#pragma unroll
            for (int jj = 0; jj < 4; jj++)
                wmma::load_matrix_sync(bf[jj], &Bs[(wn * 64 + jj * 16) * LDTH + kk], LDTH);
#pragma unroll
            for (int i = 0; i < 2; i++)
#pragma unroll
                for (int jj = 0; jj < 4; jj++)
                    wmma::mma_sync(acc[i][jj], af[i], bf[jj], acc[i][jj]);
        }
    }

#pragma unroll
    for (int i = 0; i < 2; i++)
#pragma unroll
        for (int j = 0; j < 4; j++)
            wmma::store_matrix_sync(
                &C[(size_t)(bm + wm * 32 + i * 16) * N + bn + wn * 64 + j * 16],
                acc[i][j], N, wmma::mem_row_major);
}

// ---------------------------------------------------------------------------
// GEMM2: tf32 WMMA (pre-rounded inputs), fp32 acc.
// CTA 128x128, 8 warps, warp tile 32x64. 3-stage ring.
// ---------------------------------------------------------------------------
constexpr int TKF  = 32;
constexpr int LDTF = 36;
constexpr int STGF = 256 * LDTF;
#define SMEM_GT (3 * STGF * 4)       // 110592 bytes

__global__ void __launch_bounds__(256, 2) gemm_bt(const float* __restrict__ A,
                                                  const float* __restrict__ B,
                                                  float* __restrict__ C,
                                                  int M, int N, int K) {
    extern __shared__ __align__(16) float smf2[];
    const int tid  = threadIdx.x;
    const int warp = tid >> 5;
    const int wm   = warp >> 1, wn = warp & 1;
    const int bm   = blockIdx.y * 128, bn = blockIdx.x * 128;

    wmma::fragment<wmma::accumulator, 16, 16, 8, float> acc[2][4];
#pragma unroll
    for (int i = 0; i < 2; i++)
#pragma unroll
        for (int j = 0; j < 4; j++) wmma::fill_fragment(acc[i][j], 0.0f);

    const int lrow = tid >> 3;
    const int lcol = (tid & 7) << 2;

    auto load_stage = [&](int s, int k0) {
        float* As = smf2 + s * STGF;
        float* Bs = As + 128 * LDTF;
#pragma unroll
        for (int t = 0; t < 4; t++) {
            int r = lrow + t * 32;
            cp_async16(&As[r * LDTF + lcol], &A[(size_t)(bm + r) * K + k0 + lcol]);
        }
#pragma unroll
        for (int t = 0; t < 4; t++) {
            int r = lrow + t * 32;
            cp_async16(&Bs[r * LDTF + lcol], &B[(size_t)(bn + r) * K + k0 + lcol]);
        }
        asm volatile("cp.async.commit_group;\n" ::: "memory");
    };

    load_stage(0, 0);
    load_stage(1, TKF);

    const int niter = K / TKF;   // 32
    for (int j = 0; j < niter; j++) {
        asm volatile("cp.async.wait_group 1;\n" ::: "memory");
        __syncthreads();
        if (j + 2 < niter) load_stage((j + 2) % 3, (j + 2) * TKF);

        const float* As = smf2 + (j % 3) * STGF;
        const float* Bs = As + 128 * LDTF;
#pragma unroll
        for (int kk = 0; kk < TKF; kk += 8) {
            wmma::fragment<wmma::matrix_a, 16, 16, 8, wmma::precision::tf32,
                           wmma::row_major> af[2];
            wmma::fragment<wmma::matrix_b, 16, 16, 8, wmma::precision::tf32,
                           wmma::col_major> bf[4];
#pragma unroll
            for (int i = 0; i < 2; i++)
                wmma::load_matrix_sync(af[i], &As[(wm * 32 + i * 16) * LDTF + kk], LDTF);
#pragma unroll
            for (int jj = 0; jj < 4; jj++)
                wmma::load_matrix_sync(bf[jj], &Bs[(wn * 64 + jj * 16) * LDTF + kk], LDTF);
#pragma unroll
            for (int i = 0; i < 2; i++)
#pragma unroll
                for (int jj = 0; jj < 4; jj++)
                    wmma::mma_sync(acc[i][jj], af[i], bf[jj], acc[i][jj]);
        }
    }

#pragma unroll
    for (int i = 0; i < 2; i++)
#pragma unroll
        for (int j = 0; j < 4; j++)
            wmma::store_matrix_sync(
                &C[(size_t)(bm + wm * 32 + i * 16) * N + bn + wn * 64 + j * 16],
                acc[i][j], N, wmma::mem_row_major);
}

// ---------------------------------------------------------------------------
// Fused attention v3: one CTA per (b, h). Both matmuls on fp16 tensor cores.
//  - LN fused with gmem load (fp32) -> Q/K half
//  - S = Q K^T fp16 TC (warps 0-4) while warps 5-7 load V -> half
//  - softmax fp32 (bias folded), P -> half into zero-padded 80x88 tile
//  - O = P V fp16 TC, fp32 acc -> smem -> tf32-rounded gmem store
// ---------------------------------------------------------------------------
#define LDQH  72                       // half ld for qh/kh/vh (144B rows)
#define LDPH  88                       // half ld for P tile (176B rows)
#define LDS2  84                       // fp32 ld for S/O tile
#define ATT_QH 0                       // 80*72*2  = 11520
#define ATT_KH 11520                   // 80*72*2  = 11520
#define ATT_VH 23040                   // 80*72*2  = 11520
#define ATT_PH 34560                   // 80*88*2  = 14080
#define ATT_S  48640                   // 80*84*4  = 26880
#define SMEM_ATT3 75520

__global__ void __launch_bounds__(256) attn_kernel(
    const float* __restrict__ qkv, const float* __restrict__ bias,
    const float* __restrict__ bscale_p,
    const float* __restrict__ qn_w, const float* __restrict__ qn_b,
    const float* __restrict__ kn_w, const float* __restrict__ kn_b,
    float* __restrict__ outp) {
    extern __shared__ __align__(16) char smc[];
    __half* qh  = (__half*)(smc + ATT_QH);
    __half* kh  = (__half*)(smc + ATT_KH);
    __half* vh  = (__half*)(smc + ATT_VH);
    __half* ph  = (__half*)(smc + ATT_PH);
    float*  s_s = (float*)(smc + ATT_S);

    const int tid = threadIdx.x, lane = tid & 31, warp = tid >> 5;
    const int h = blockIdx.x, b = blockIdx.y;
    const float bscale = *bscale_p;
    const size_t base = (size_t)b * SEQ * 3072 + (size_t)h * 64;

    // zero: full P tile (3520 u32) + vh pad rows 65..79 (540 u32)
    {
        unsigned* phz = (unsigned*)ph;
        for (int i = tid; i < 3520; i += 256) phz[i] = 0u;
        unsigned* vhz = (unsigned*)vh + 65 * (LDQH / 2);
        for (int i = tid; i < 15 * (LDQH / 2); i += 256) vhz[i] = 0u;
    }

    // fused gmem load + LayerNorm -> half (q scaled by hd^-0.5)
    const float qw0 = qn_w[lane], qw1 = qn_w[lane + 32];
    const float qb0 = qn_b[lane], qb1 = qn_b[lane + 32];
    const float kw0 = kn_w[lane], kw1 = kn_w[lane + 32];
    const float kb0 = kn_b[lane], kb1 = kn_b[lane + 32];
    for (int n = warp; n < SEQ; n += 8) {
        float x0 = qkv[base + (size_t)n * 3072 + lane];
        float x1 = qkv[base + (size_t)n * 3072 + lane + 32];
        float s = x0 + x1, sq = x0 * x0 + x1 * x1;
#pragma unroll
        for (int o = 16; o; o >>= 1) {
            s += __shfl_xor_sync(0xffffffffu, s, o);
            sq += __shfl_xor_sync(0xffffffffu, sq, o);
        }
        float mu = s * (1.f / 64.f);
        float rstd = rsqrtf(sq * (1.f / 64.f) - mu * mu + 1e-5f);
        qh[n * LDQH + lane]      = __float2half(((x0 - mu) * rstd * qw0 + qb0) * 0.125f);
        qh[n * LDQH + lane + 32] = __float2half(((x1 - mu) * rstd * qw1 + qb1) * 0.125f);

        x0 = qkv[base + (size_t)n * 3072 + 1024 + lane];
        x1 = qkv[base + (size_t)n * 3072 + 1024 + lane + 32];
        s = x0 + x1; sq = x0 * x0 + x1 * x1;
#pragma unroll
        for (int o = 16; o; o >>= 1) {
            s += __shfl_xor_sync(0xffffffffu, s, o);
            sq += __shfl_xor_sync(0xffffffffu, sq, o);
        }
        mu = s * (1.f / 64.f);
        rstd = rsqrtf(sq * (1.f / 64.f) - mu * mu + 1e-5f);
        kh[n * LDQH + lane]      = __float2half((x0 - mu) * rstd * kw0 + kb0);
        kh[n * LDQH + lane + 32] = __float2half((x1 - mu) * rstd * kw1 + kb1);
    }
    __syncthreads();

    // S = Q K^T (warps 0-4, 16-row strips); warps 5-7 load V -> half
    if (warp < 5) {
        wmma::fragment<wmma::accumulator, 16, 16, 16, float> sacc[5];
#pragma unroll
        for (int m = 0; m < 5; m++) wmma::fill_fragment(sacc[m], 0.0f);
#pragma unroll
        for (int kk = 0; kk < 4; kk++) {
            wmma::fragment<wmma::matrix_a, 16, 16, 16, __half, wmma::row_major> aq;
            wmma::load_matrix_sync(aq, &qh[warp * 16 * LDQH + kk * 16], LDQH);
#pragma unroll
            for (int m = 0; m < 5; m++) {
                wmma::fragment<wmma::matrix_b, 16, 16, 16, __half, wmma::col_major> bk;
                wmma::load_matrix_sync(bk, &kh[m * 16 * LDQH + kk * 16], LDQH);
                wmma::mma_sync(sacc[m], aq, bk, sacc[m]);
            }
        }
#pragma unroll
        for (int m = 0; m < 5; m++)
            wmma::store_matrix_sync(&s_s[warp * 16 * LDS2 + m * 16], sacc[m],
                                    LDS2, wmma::mem_row_major);
    } else {
        for (int i = tid - 160; i < SEQ * 64; i += 96) {
            int n = i >> 6, d = i & 63;
            vh[n * LDQH + d] =
                __float2half(qkv[base + (size_t)n * 3072 + 2048 + d]);
        }
    }
    __syncthreads();

    // softmax rows (fp32, bias folded); write P as half
    for (int n = warp; n < SEQ; n += 8) {
        const float* brow = &bias[((size_t)h * SEQ + n) * SEQ];
        float v0 = s_s[n * LDS2 + lane]      + brow[lane] * bscale;
        float v1 = s_s[n * LDS2 + lane + 32] + brow[lane + 32] * bscale;
        float v2 = (lane == 0) ? s_s[n * LDS2 + 64] + brow[64] * bscale : -3.4e38f;
        float mx = fmaxf(fmaxf(v0, v1), v2);
#pragma unroll
        for (int o = 16; o; o >>= 1) mx = fmaxf(mx, __shfl_xor_sync(0xffffffffu, mx, o));
        float e0 = __expf(v0 - mx), e1 = __expf(v1 - mx);
        float e2 = (lane == 0) ? __expf(v2 - mx) : 0.f;
        float sum = e0 + e1 + e2;
#pragma unroll
        for (int o = 16; o; o >>= 1) sum += __shfl_xor_sync(0xffffffffu, sum, o);
        float inv = 1.f / sum;
        ph[n * LDPH + lane]      = __float2half(e0 * inv);
        ph[n * LDPH + lane + 32] = __float2half(e1 * inv);
        if (lane == 0) ph[n * LDPH + 64] = __float2half(e2 * inv);
    }
    __syncthreads();

    // O = P V on tensor cores (warps 0-4, 16-row strips, 64 cols)
    if (warp < 5) {
        wmma::fragment<wmma::accumulator, 16, 16, 16, float> oacc[4];
#pragma unroll
        for (int j = 0; j < 4; j++) wmma::fill_fragment(oacc[j], 0.0f);
#pragma unroll
        for (int kk = 0; kk < 5; kk++) {
            wmma::fragment<wmma::matrix_a, 16, 16, 16, __half, wmma::row_major> ap;
            wmma::load_matrix_sync(ap, &ph[warp * 16 * LDPH + kk * 16], LDPH);
#pragma unroll
            for (int j = 0; j < 4; j++) {
                wmma::fragment<wmma::matrix_b, 16, 16, 16, __half, wmma::row_major> bv;
                wmma::load_matrix_sync(bv, &vh[kk * 16 * LDQH + j * 16], LDQH);
                wmma::mma_sync(oacc[j], ap, bv, oacc[j]);
            }
        }
#pragma unroll
        for (int j = 0; j < 4; j++)
            wmma::store_matrix_sync(&s_s[warp * 16 * LDS2 + j * 16], oacc[j],
                                    LDS2, wmma::mem_row_major);
    }
    __syncthreads();

    // epilogue: rows<65, cols<64 -> gmem with tf32 round (feeds tf32 GEMM2)
    for (int i = tid; i < SEQ * 64; i += 256) {
        int n = i >> 6, d = i & 63;
        outp[((size_t)b * SEQ + n) * DIMC + (size_t)h * 64 + d] =
            tf32r(s_s[n * LDS2 + d]);
    }
}

// ---------------------------------------------------------------------------
extern "C" void kernel_launch(void* const* d_in, const int* in_sizes, int n_in,
                              void* d_out, int out_size) {
    const float* x      = (const float*)d_in[0];
    const float* w_qkv  = (const float*)d_in[1];
    const float* w_proj = (const float*)d_in[2];
    const float* qn_w   = (const float*)d_in[3];
    const float* qn_b   = (const float*)d_in[4];
    const float* kn_w   = (const float*)d_in[5];
    const float* kn_b   = (const float*)d_in[6];
    const float* bias   = (const float*)d_in[7];
    const float* bscale = (const float*)d_in[8];
    float* out          = (float*)d_out;

    float *qkv_p, *att_p, *wprojr_p;
    __half *xh_p, *wqkvh_p;
    cudaGetSymbolAddress((void**)&qkv_p, g_qkv);
    cudaGetSymbolAddress((void**)&att_p, g_att);
    cudaGetSymbolAddress((void**)&xh_p, g_xh);
    cudaGetSymbolAddress((void**)&wqkvh_p, g_wqkvh);
    cudaGetSymbolAddress((void**)&wprojr_p, g_wprojr);

    cudaFuncSetAttribute(gemm_h, cudaFuncAttributeMaxDynamicSharedMemorySize,
                         SMEM_GH);
    cudaFuncSetAttribute(gemm_bt, cudaFuncAttributeMaxDynamicSharedMemorySize,
                         SMEM_GT);
    cudaFuncSetAttribute(attn_kernel, cudaFuncAttributeMaxDynamicSharedMemorySize,
                         SMEM_ATT3);

    // 0) operand converts: fp16 for GEMM1, tf32 for GEMM2 weights
    int n4x = MROWS * DIMC / 4;
    f2h_k<<<(n4x + 255) / 256, 256>>>((const float4*)x, (__half2*)xh_p, n4x);
    int n4wq = 3 * DIMC * DIMC / 4;
    f2h_k<<<(n4wq + 255) / 256, 256>>>((const float4*)w_qkv, (__half2*)wqkvh_p, n4wq);
    int n4wp = DIMC * DIMC / 4;
    round_tf32_k<<<(n4wp + 255) / 256, 256>>>(w_proj, wprojr_p, n4wp);

    // 1) QKV projection (fp16 tensor): [33280,1024] x [3072,1024]^T
    gemm_h<<<dim3(3 * DIMC / 128, MROWS / 128), 256, SMEM_GH>>>(
        xh_p, wqkvh_p, qkv_p, MROWS, 3 * DIMC, DIMC);
    // 2) Fused LN + attention per (b,h); QK^T and PV on tensor cores
    attn_kernel<<<dim3(HEADS, BATCH), 256, SMEM_ATT3>>>(
        qkv_p, bias, bscale, qn_w, qn_b, kn_w, kn_b, att_p);
    // 3) Output projection (tf32 tensor): [33280,1024] x [1024,1024]^T
    gemm_bt<<<dim3(DIMC / 128, MROWS / 128), 256, SMEM_GT>>>(
        att_p, wprojr_p, out, MROWS, DIMC, DIMC);
}

// round 15
// speedup vs baseline: 2.9475x; 1.2043x over previous
#include <cuda_runtime.h>
#include <cuda_fp16.h>
#include <cstdint>
#include <mma.h>
using namespace nvcuda;

#define DIMC   1024
#define HEADS  16
#define HD     64
#define BATCH  512
#define SEQ    65
#define MROWS  (BATCH * SEQ)   // 33280 = 260*128

// Scratch (allocation-free rule: __device__ globals)
__device__ float  g_qkv[(size_t)MROWS * 3 * DIMC];    // GEMM1 out (fp32)
__device__ __half g_xh[(size_t)MROWS * DIMC];         // x -> half
__device__ __half g_wqkvh[(size_t)3 * DIMC * DIMC];   // w_qkv -> half
__device__ __half g_oh[(size_t)MROWS * DIMC];         // attn out hi
__device__ __half g_ol[(size_t)MROWS * DIMC];         // attn out lo
__device__ __half g_wph[(size_t)DIMC * DIMC];         // w_proj hi
__device__ __half g_wpl[(size_t)DIMC * DIMC];         // w_proj lo

// ---------------------------------------------------------------------------
// converts
// ---------------------------------------------------------------------------
__global__ void __launch_bounds__(256) f2h_k(const float4* __restrict__ in,
                                             __half2* __restrict__ out, int n4) {
    int i = blockIdx.x * blockDim.x + threadIdx.x;
    if (i < n4) {
        float4 v = in[i];
        out[2 * i]     = __floats2half2_rn(v.x, v.y);
        out[2 * i + 1] = __floats2half2_rn(v.z, v.w);
    }
}

// split: hi = fp16(x), lo = fp16(x - hi)
__global__ void __launch_bounds__(256) f2hsplit_k(const float4* __restrict__ in,
                                                  __half2* __restrict__ hi,
                                                  __half2* __restrict__ lo, int n4) {
    int i = blockIdx.x * blockDim.x + threadIdx.x;
    if (i < n4) {
        float4 v = in[i];
        __half2 h0 = __floats2half2_rn(v.x, v.y);
        __half2 h1 = __floats2half2_rn(v.z, v.w);
        float2 f0 = __half22float2(h0), f1 = __half22float2(h1);
        hi[2 * i]     = h0;
        hi[2 * i + 1] = h1;
        lo[2 * i]     = __floats2half2_rn(v.x - f0.x, v.y - f0.y);
        lo[2 * i + 1] = __floats2half2_rn(v.z - f1.x, v.w - f1.y);
    }
}

__device__ __forceinline__ void cp_async16(void* smem, const void* gmem) {
    unsigned s = (unsigned)__cvta_generic_to_shared(smem);
    asm volatile("cp.async.cg.shared.global [%0], [%1], 16;\n" ::"r"(s), "l"(gmem));
}

// ---------------------------------------------------------------------------
// GEMM1: fp16 WMMA m16n16k16, fp32 acc. C = A[M,K] * B[N,K]^T.
// CTA 128x128, 8 warps (4Mx2N), warp tile 32x64. 3-stage cp.async ring.
// ---------------------------------------------------------------------------
constexpr int TKH  = 64;
constexpr int LDTH = 72;
constexpr int STGH = 256 * LDTH;
#define SMEM_GH (3 * STGH * 2)       // 110592 bytes

__global__ void __launch_bounds__(256, 2) gemm_h(const __half* __restrict__ A,
                                                 const __half* __restrict__ B,
                                                 float* __restrict__ C,
                                                 int M, int N, int K) {
    extern __shared__ __align__(16) __half smh[];
    const int tid  = threadIdx.x;
    const int warp = tid >> 5;
    const int wm   = warp >> 1, wn = warp & 1;
    const int bm   = blockIdx.y * 128, bn = blockIdx.x * 128;

    wmma::fragment<wmma::accumulator, 16, 16, 16, float> acc[2][4];
#pragma unroll
    for (int i = 0; i < 2; i++)
#pragma unroll
        for (int j = 0; j < 4; j++) wmma::fill_fragment(acc[i][j], 0.0f);

    const int lrow = tid >> 3;
    const int lcol = (tid & 7) << 3;

    auto load_stage = [&](int s, int k0) {
        __half* As = smh + s * STGH;
        __half* Bs = As + 128 * LDTH;
#pragma unroll
        for (int t = 0; t < 4; t++) {
            int r = lrow + t * 32;
            cp_async16(&As[r * LDTH + lcol], &A[(size_t)(bm + r) * K + k0 + lcol]);
        }
#pragma unroll
        for (int t = 0; t < 4; t++) {
            int r = lrow + t * 32;
            cp_async16(&Bs[r * LDTH + lcol], &B[(size_t)(bn + r) * K + k0 + lcol]);
        }
        asm volatile("cp.async.commit_group;\n" ::: "memory");
    };

    load_stage(0, 0);
    load_stage(1, TKH);

    const int niter = K / TKH;   // 16
    for (int j = 0; j < niter; j++) {
        asm volatile("cp.async.wait_group 1;\n" ::: "memory");
        __syncthreads();
        if (j + 2 < niter) load_stage((j + 2) % 3, (j + 2) * TKH);

        const __half* As = smh + (j % 3) * STGH;
        const __half* Bs = As + 128 * LDTH;
#pragma unroll
        for (int kk = 0; kk < TKH; kk += 16) {
            wmma::fragment<wmma::matrix_a, 16, 16, 16, __half, wmma::row_major> af[2];
            wmma::fragment<wmma::matrix_b, 16, 16, 16, __half, wmma::col_major> bf[4];
#pragma unroll
            for (int i = 0; i < 2; i++)
                wmma::load_matrix_sync(af[i], &As[(wm * 32 + i * 16) * LDTH + kk], LDTH);
#pragma unroll
            for (int jj = 0; jj < 4; jj++)
                wmma::load_matrix_sync(bf[jj], &Bs[(wn * 64 + jj * 16) * LDTH + kk], LDTH);
#pragma unroll
            for (int i = 0; i < 2; i++)
#pragma unroll
                for (int jj = 0; jj < 4; jj++)
                    wmma::mma_sync(acc[i][jj], af[i], bf[jj], acc[i][jj]);
        }
    }

#pragma unroll
    for (int i = 0; i < 2; i++)
#pragma unroll
        for (int j = 0; j < 4; j++)
            wmma::store_matrix_sync(
                &C[(size_t)(bm + wm * 32 + i * 16) * N + bn + wn * 64 + j * 16],
                acc[i][j], N, wmma::mem_row_major);
}

// ---------------------------------------------------------------------------
// GEMM2 (split-fp16): C = Ah*Bh^T + Ah*Bl^T + Al*Bh^T, fp32 acc.
// More accurate than tf32; runs on the fast fp16 HMMA path.
// CTA 128x128, 8 warps (4Mx2N), warp tile 32x64. 2-stage ring, K=32/stage.
// Stage layout (halfs, ld 40): Ah[0:128) Al[128:256) Bh[256:384) Bl[384:512)
// ---------------------------------------------------------------------------
constexpr int TKS  = 32;
constexpr int LDSP = 40;
constexpr int STGS = 512 * LDSP;     // halfs per stage
#define SMEM_SP (2 * STGS * 2)       // 81920 bytes

__global__ void __launch_bounds__(256, 2) gemm_sp(const __half* __restrict__ Ah,
                                                  const __half* __restrict__ Al,
                                                  const __half* __restrict__ Bh,
                                                  const __half* __restrict__ Bl,
                                                  float* __restrict__ C,
                                                  int M, int N, int K) {
    extern __shared__ __align__(16) __half sms[];
    const int tid  = threadIdx.x;
    const int warp = tid >> 5;
    const int wm   = warp >> 1, wn = warp & 1;
    const int bm   = blockIdx.y * 128, bn = blockIdx.x * 128;

    wmma::fragment<wmma::accumulator, 16, 16, 16, float> acc[2][4];
#pragma unroll
    for (int i = 0; i < 2; i++)
#pragma unroll
        for (int j = 0; j < 4; j++) wmma::fill_fragment(acc[i][j], 0.0f);

    const int lrow = tid >> 2;          // 0..63
    const int lcol = (tid & 3) << 3;    // 0,8,16,24 halfs (16B chunks)

    auto load_stage = [&](int s, int k0) {
        __half* stg = sms + s * STGS;
#pragma unroll
        for (int t = 0; t < 8; t++) {
            int row = lrow + t * 64;            // 0..511
            int g = row >> 7, r = row & 127;
            const __half* src =
                (g == 0) ? &Ah[(size_t)(bm + r) * K + k0 + lcol]
              : (g == 1) ? &Al[(size_t)(bm + r) * K + k0 + lcol]
              : (g == 2) ? &Bh[(size_t)(bn + r) * K + k0 + lcol]
                         : &Bl[(size_t)(bn + r) * K + k0 + lcol];
            cp_async16(&stg[row * LDSP + lcol], src);
        }
        asm volatile("cp.async.commit_group;\n" ::: "memory");
    };

    load_stage(0, 0);

    const int niter = K / TKS;   // 32
    for (int j = 0; j < niter; j++) {
        if (j + 1 < niter) load_stage((j + 1) & 1, (j + 1) * TKS);
        else asm volatile("cp.async.commit_group;\n" ::: "memory");
        asm volatile("cp.async.wait_group 1;\n" ::: "memory");
        __syncthreads();

        const __half* As_h = sms + (j & 1) * STGS;
        const __half* As_l = As_h + 128 * LDSP;
        const __half* Bs_h = As_h + 256 * LDSP;
        const __half* Bs_l = As_h + 384 * LDSP;
#pragma unroll
        for (int kk = 0; kk < TKS; kk += 16) {
            wmma::fragment<wmma::matrix_a, 16, 16, 16, __half, wmma::row_major> afh[2], afl[2];
#pragma unroll
            for (int i = 0; i < 2; i++) {
                wmma::load_matrix_sync(afh[i], &As_h[(wm * 32 + i * 16) * LDSP + kk], LDSP);
                wmma::load_matrix_sync(afl[i], &As_l[(wm * 32 + i * 16) * LDSP + kk], LDSP);
            }
#pragma unroll
            for (int jj = 0; jj < 4; jj++) {
                wmma::fragment<wmma::matrix_b, 16, 16, 16, __half, wmma::col_major> bfh, bfl;
                wmma::load_matrix_sync(bfh, &Bs_h[(wn * 64 + jj * 16) * LDSP + kk], LDSP);
                wmma::load_matrix_sync(bfl, &Bs_l[(wn * 64 + jj * 16) * LDSP + kk], LDSP);
#pragma unroll
                for (int i = 0; i < 2; i++) {
                    wmma::mma_sync(acc[i][jj], afh[i], bfh, acc[i][jj]);
                    wmma::mma_sync(acc[i][jj], afh[i], bfl, acc[i][jj]);
                    wmma::mma_sync(acc[i][jj], afl[i], bfh, acc[i][jj]);
                }
            }
        }
        __syncthreads();
    }

#pragma unroll
    for (int i = 0; i < 2; i++)
#pragma unroll
        for (int j = 0; j < 4; j++)
            wmma::store_matrix_sync(
                &C[(size_t)(bm + wm * 32 + i * 16) * N + bn + wn * 64 + j * 16],
                acc[i][j], N, wmma::mem_row_major);
}

// ---------------------------------------------------------------------------
// Fused attention v3: one CTA per (b, h). Both matmuls on fp16 tensor cores.
// Epilogue writes split-fp16 (hi, lo) for GEMM2.
// ---------------------------------------------------------------------------
#define LDQH  72
#define LDPH  88
#define LDS2  84
#define ATT_QH 0
#define ATT_KH 11520
#define ATT_VH 23040
#define ATT_PH 34560
#define ATT_S  48640
#define SMEM_ATT3 75520

__global__ void __launch_bounds__(256) attn_kernel(
    const float* __restrict__ qkv, const float* __restrict__ bias,
    const float* __restrict__ bscale_p,
    const float* __restrict__ qn_w, const float* __restrict__ qn_b,
    const float* __restrict__ kn_w, const float* __restrict__ kn_b,
    __half* __restrict__ outh, __half* __restrict__ outl) {
    extern __shared__ __align__(16) char smc[];
    __half* qh  = (__half*)(smc + ATT_QH);
    __half* kh  = (__half*)(smc + ATT_KH);
    __half* vh  = (__half*)(smc + ATT_VH);
    __half* ph  = (__half*)(smc + ATT_PH);
    float*  s_s = (float*)(smc + ATT_S);

    const int tid = threadIdx.x, lane = tid & 31, warp = tid >> 5;
    const int h = blockIdx.x, b = blockIdx.y;
    const float bscale = *bscale_p;
    const size_t base = (size_t)b * SEQ * 3072 + (size_t)h * 64;

    // zero: full P tile + vh pad rows 65..79
    {
        unsigned* phz = (unsigned*)ph;
        for (int i = tid; i < 3520; i += 256) phz[i] = 0u;
        unsigned* vhz = (unsigned*)vh + 65 * (LDQH / 2);
        for (int i = tid; i < 15 * (LDQH / 2); i += 256) vhz[i] = 0u;
    }

    // fused gmem load + LayerNorm -> half (q scaled by hd^-0.5)
    const float qw0 = qn_w[lane], qw1 = qn_w[lane + 32];
    const float qb0 = qn_b[lane], qb1 = qn_b[lane + 32];
    const float kw0 = kn_w[lane], kw1 = kn_w[lane + 32];
    const float kb0 = kn_b[lane], kb1 = kn_b[lane + 32];
    for (int n = warp; n < SEQ; n += 8) {
        float x0 = qkv[base + (size_t)n * 3072 + lane];
        float x1 = qkv[base + (size_t)n * 3072 + lane + 32];
        float s = x0 + x1, sq = x0 * x0 + x1 * x1;
#pragma unroll
        for (int o = 16; o; o >>= 1) {
            s += __shfl_xor_sync(0xffffffffu, s, o);
            sq += __shfl_xor_sync(0xffffffffu, sq, o);
        }
        float mu = s * (1.f / 64.f);
        float rstd = rsqrtf(sq * (1.f / 64.f) - mu * mu + 1e-5f);
        qh[n * LDQH + lane]      = __float2half(((x0 - mu) * rstd * qw0 + qb0) * 0.125f);
        qh[n * LDQH + lane + 32] = __float2half(((x1 - mu) * rstd * qw1 + qb1) * 0.125f);

        x0 = qkv[base + (size_t)n * 3072 + 1024 + lane];
        x1 = qkv[base + (size_t)n * 3072 + 1024 + lane + 32];
        s = x0 + x1; sq = x0 * x0 + x1 * x1;
#pragma unroll
        for (int o = 16; o; o >>= 1) {
            s += __shfl_xor_sync(0xffffffffu, s, o);
            sq += __shfl_xor_sync(0xffffffffu, sq, o);
        }
        mu = s * (1.f / 64.f);
        rstd = rsqrtf(sq * (1.f / 64.f) - mu * mu + 1e-5f);
        kh[n * LDQH + lane]      = __float2half((x0 - mu) * rstd * kw0 + kb0);
        kh[n * LDQH + lane + 32] = __float2half((x1 - mu) * rstd * kw1 + kb1);
    }
    __syncthreads();

    // S = Q K^T (warps 0-4); warps 5-7 load V -> half
    if (warp < 5) {
        wmma::fragment<wmma::accumulator, 16, 16, 16, float> sacc[5];
#pragma unroll
        for (int m = 0; m < 5; m++) wmma::fill_fragment(sacc[m], 0.0f);
#pragma unroll
        for (int kk = 0; kk < 4; kk++) {
            wmma::fragment<wmma::matrix_a, 16, 16, 16, __half, wmma::row_major> aq;
            wmma::load_matrix_sync(aq, &qh[warp * 16 * LDQH + kk * 16], LDQH);
#pragma unroll
            for (int m = 0; m < 5; m++) {
                wmma::fragment<wmma::matrix_b, 16, 16, 16, __half, wmma::col_major> bk;
                wmma::load_matrix_sync(bk, &kh[m * 16 * LDQH + kk * 16], LDQH);
                wmma::mma_sync(sacc[m], aq, bk, sacc[m]);
            }
        }
#pragma unroll
        for (int m = 0; m < 5; m++)
            wmma::store_matrix_sync(&s_s[warp * 16 * LDS2 + m * 16], sacc[m],
                                    LDS2, wmma::mem_row_major);
    } else {
        for (int i = tid - 160; i < SEQ * 64; i += 96) {
            int n = i >> 6, d = i & 63;
            vh[n * LDQH + d] =
                __float2half(qkv[base + (size_t)n * 3072 + 2048 + d]);
        }
    }
    __syncthreads();

    // softmax rows (fp32, bias folded); write P as half
    for (int n = warp; n < SEQ; n += 8) {
        const float* brow = &bias[((size_t)h * SEQ + n) * SEQ];
        float v0 = s_s[n * LDS2 + lane]      + brow[lane] * bscale;
        float v1 = s_s[n * LDS2 + lane + 32] + brow[lane + 32] * bscale;
        float v2 = (lane == 0) ? s_s[n * LDS2 + 64] + brow[64] * bscale : -3.4e38f;
        float mx = fmaxf(fmaxf(v0, v1), v2);
#pragma unroll
        for (int o = 16; o; o >>= 1) mx = fmaxf(mx, __shfl_xor_sync(0xffffffffu, mx, o));
        float e0 = __expf(v0 - mx), e1 = __expf(v1 - mx);
        float e2 = (lane == 0) ? __expf(v2 - mx) : 0.f;
        float sum = e0 + e1 + e2;
#pragma unroll
        for (int o = 16; o; o >>= 1) sum += __shfl_xor_sync(0xffffffffu, sum, o);
        float inv = 1.f / sum;
        ph[n * LDPH + lane]      = __float2half(e0 * inv);
        ph[n * LDPH + lane + 32] = __float2half(e1 * inv);
        if (lane == 0) ph[n * LDPH + 64] = __float2half(e2 * inv);
    }
    __syncthreads();

    // O = P V on tensor cores (warps 0-4)
    if (warp < 5) {
        wmma::fragment<wmma::accumulator, 16, 16, 16, float> oacc[4];
#pragma unroll
        for (int j = 0; j < 4; j++) wmma::fill_fragment(oacc[j], 0.0f);
#pragma unroll
        for (int kk = 0; kk < 5; kk++) {
            wmma::fragment<wmma::matrix_a, 16, 16, 16, __half, wmma::row_major> ap;
            wmma::load_matrix_sync(ap, &ph[warp * 16 * LDPH + kk * 16], LDPH);
#pragma unroll
            for (int j = 0; j < 4; j++) {
                wmma::fragment<wmma::matrix_b, 16, 16, 16, __half, wmma::row_major> bv;
                wmma::load_matrix_sync(bv, &vh[kk * 16 * LDQH + j * 16], LDQH);
                wmma::mma_sync(oacc[j], ap, bv, oacc[j]);
            }
        }
#pragma unroll
        for (int j = 0; j < 4; j++)
            wmma::store_matrix_sync(&s_s[warp * 16 * LDS2 + j * 16], oacc[j],
                                    LDS2, wmma::mem_row_major);
    }
    __syncthreads();

    // epilogue: split-fp16 write (hi, lo) -> feeds split GEMM2
    for (int i = tid; i < SEQ * 64; i += 256) {
        int n = i >> 6, d = i & 63;
        float v = s_s[n * LDS2 + d];
        __half hh = __float2half_rn(v);
        __half ll = __float2half_rn(v - __half2float(hh));
        size_t o = ((size_t)b * SEQ + n) * DIMC + (size_t)h * 64 + d;
        outh[o] = hh;
        outl[o] = ll;
    }
}

// ---------------------------------------------------------------------------
extern "C" void kernel_launch(void* const* d_in, const int* in_sizes, int n_in,
                              void* d_out, int out_size) {
    const float* x      = (const float*)d_in[0];
    const float* w_qkv  = (const float*)d_in[1];
    const float* w_proj = (const float*)d_in[2];
    const float* qn_w   = (const float*)d_in[3];
    const float* qn_b   = (const float*)d_in[4];
    const float* kn_w   = (const float*)d_in[5];
    const float* kn_b   = (const float*)d_in[6];
    const float* bias   = (const float*)d_in[7];
    const float* bscale = (const float*)d_in[8];
    float* out          = (float*)d_out;

    float* qkv_p;
    __half *xh_p, *wqkvh_p, *oh_p, *ol_p, *wph_p, *wpl_p;
    cudaGetSymbolAddress((void**)&qkv_p, g_qkv);
    cudaGetSymbolAddress((void**)&xh_p, g_xh);
    cudaGetSymbolAddress((void**)&wqkvh_p, g_wqkvh);
    cudaGetSymbolAddress((void**)&oh_p, g_oh);
    cudaGetSymbolAddress((void**)&ol_p, g_ol);
    cudaGetSymbolAddress((void**)&wph_p, g_wph);
    cudaGetSymbolAddress((void**)&wpl_p, g_wpl);

    cudaFuncSetAttribute(gemm_h, cudaFuncAttributeMaxDynamicSharedMemorySize,
                         SMEM_GH);
    cudaFuncSetAttribute(gemm_sp, cudaFuncAttributeMaxDynamicSharedMemorySize,
                         SMEM_SP);
    cudaFuncSetAttribute(attn_kernel, cudaFuncAttributeMaxDynamicSharedMemorySize,
                         SMEM_ATT3);

    // 0) operand converts: fp16 for GEMM1; split-fp16 for w_proj
    int n4x = MROWS * DIMC / 4;
    f2h_k<<<(n4x + 255) / 256, 256>>>((const float4*)x, (__half2*)xh_p, n4x);
    int n4wq = 3 * DIMC * DIMC / 4;
    f2h_k<<<(n4wq + 255) / 256, 256>>>((const float4*)w_qkv, (__half2*)wqkvh_p, n4wq);
    int n4wp = DIMC * DIMC / 4;
    f2hsplit_k<<<(n4wp + 255) / 256, 256>>>((const float4*)w_proj,
                                            (__half2*)wph_p, (__half2*)wpl_p, n4wp);

    // 1) QKV projection (fp16 tensor): [33280,1024] x [3072,1024]^T
    gemm_h<<<dim3(3 * DIMC / 128, MROWS / 128), 256, SMEM_GH>>>(
        xh_p, wqkvh_p, qkv_p, MROWS, 3 * DIMC, DIMC);
    // 2) Fused LN + attention per (b,h); writes split-fp16 output
    attn_kernel<<<dim3(HEADS, BATCH), 256, SMEM_ATT3>>>(
        qkv_p, bias, bscale, qn_w, qn_b, kn_w, kn_b, oh_p, ol_p);
    // 3) Output projection (split-fp16, 3-term): [33280,1024] x [1024,1024]^T
    gemm_sp<<<dim3(DIMC / 128, MROWS / 128), 256, SMEM_SP>>>(
        oh_p, ol_p, wph_p, wpl_p, out, MROWS, DIMC, DIMC);
}

// round 16
// speedup vs baseline: 3.3859x; 1.1487x over previous
#include <cuda_runtime.h>
#include <cuda_fp16.h>
#include <cstdint>
#include <mma.h>
using namespace nvcuda;

#define DIMC   1024
#define HEADS  16
#define HD     64
#define BATCH  512
#define SEQ    65
#define MROWS  (BATCH * SEQ)   // 33280 = 260*128

// Scratch (allocation-free rule: __device__ globals)
__device__ float  g_qkv[(size_t)MROWS * 3 * DIMC];    // GEMM1 out (fp32)
__device__ __half g_xh[(size_t)MROWS * DIMC];         // x -> half
__device__ __half g_wqkvh[(size_t)3 * DIMC * DIMC];   // w_qkv -> half
__device__ __half g_oh[(size_t)MROWS * DIMC];         // attn out hi
__device__ __half g_ol[(size_t)MROWS * DIMC];         // attn out lo
__device__ __half g_wph[(size_t)DIMC * DIMC];         // w_proj hi
__device__ __half g_wpl[(size_t)DIMC * DIMC];         // w_proj lo

// ---------------------------------------------------------------------------
// converts
// ---------------------------------------------------------------------------
__global__ void __launch_bounds__(256) f2h_k(const float4* __restrict__ in,
                                             __half2* __restrict__ out, int n4) {
    int i = blockIdx.x * blockDim.x + threadIdx.x;
    if (i < n4) {
        float4 v = in[i];
        out[2 * i]     = __floats2half2_rn(v.x, v.y);
        out[2 * i + 1] = __floats2half2_rn(v.z, v.w);
    }
}

// split: hi = fp16(x), lo = fp16(x - hi)
__global__ void __launch_bounds__(256) f2hsplit_k(const float4* __restrict__ in,
                                                  __half2* __restrict__ hi,
                                                  __half2* __restrict__ lo, int n4) {
    int i = blockIdx.x * blockDim.x + threadIdx.x;
    if (i < n4) {
        float4 v = in[i];
        __half2 h0 = __floats2half2_rn(v.x, v.y);
        __half2 h1 = __floats2half2_rn(v.z, v.w);
        float2 f0 = __half22float2(h0), f1 = __half22float2(h1);
        hi[2 * i]     = h0;
        hi[2 * i + 1] = h1;
        lo[2 * i]     = __floats2half2_rn(v.x - f0.x, v.y - f0.y);
        lo[2 * i + 1] = __floats2half2_rn(v.z - f1.x, v.w - f1.y);
    }
}

__device__ __forceinline__ void cp_async16(void* smem, const void* gmem) {
    unsigned s = (unsigned)__cvta_generic_to_shared(smem);
    asm volatile("cp.async.cg.shared.global [%0], [%1], 16;\n" ::"r"(s), "l"(gmem));
}

// ---------------------------------------------------------------------------
// GEMM1: fp16 WMMA m16n16k16, fp32 acc. C = A[M,K] * B[N,K]^T.
// CTA 128x128, 8 warps (4Mx2N), warp tile 32x64. 3-stage cp.async ring.
// ---------------------------------------------------------------------------
constexpr int TKH  = 64;
constexpr int LDTH = 72;
constexpr int STGH = 256 * LDTH;
#define SMEM_GH (3 * STGH * 2)       // 110592 bytes

__global__ void __launch_bounds__(256, 2) gemm_h(const __half* __restrict__ A,
                                                 const __half* __restrict__ B,
                                                 float* __restrict__ C,
                                                 int M, int N, int K) {
    extern __shared__ __align__(16) __half smh[];
    const int tid  = threadIdx.x;
    const int warp = tid >> 5;
    const int wm   = warp >> 1, wn = warp & 1;
    const int bm   = blockIdx.y * 128, bn = blockIdx.x * 128;

    wmma::fragment<wmma::accumulator, 16, 16, 16, float> acc[2][4];
#pragma unroll
    for (int i = 0; i < 2; i++)
#pragma unroll
        for (int j = 0; j < 4; j++) wmma::fill_fragment(acc[i][j], 0.0f);

    const int lrow = tid >> 3;
    const int lcol = (tid & 7) << 3;

    auto load_stage = [&](int s, int k0) {
        __half* As = smh + s * STGH;
        __half* Bs = As + 128 * LDTH;
#pragma unroll
        for (int t = 0; t < 4; t++) {
            int r = lrow + t * 32;
            cp_async16(&As[r * LDTH + lcol], &A[(size_t)(bm + r) * K + k0 + lcol]);
        }
#pragma unroll
        for (int t = 0; t < 4; t++) {
            int r = lrow + t * 32;
            cp_async16(&Bs[r * LDTH + lcol], &B[(size_t)(bn + r) * K + k0 + lcol]);
        }
        asm volatile("cp.async.commit_group;\n" ::: "memory");
    };

    load_stage(0, 0);
    load_stage(1, TKH);

    const int niter = K / TKH;   // 16
    for (int j = 0; j < niter; j++) {
        asm volatile("cp.async.wait_group 1;\n" ::: "memory");
        __syncthreads();
        if (j + 2 < niter) load_stage((j + 2) % 3, (j + 2) * TKH);

        const __half* As = smh + (j % 3) * STGH;
        const __half* Bs = As + 128 * LDTH;
#pragma unroll
        for (int kk = 0; kk < TKH; kk += 16) {
            wmma::fragment<wmma::matrix_a, 16, 16, 16, __half, wmma::row_major> af[2];
            wmma::fragment<wmma::matrix_b, 16, 16, 16, __half, wmma::col_major> bf[4];
#pragma unroll
            for (int i = 0; i < 2; i++)
                wmma::load_matrix_sync(af[i], &As[(wm * 32 + i * 16) * LDTH + kk], LDTH);
#pragma unroll
            for (int jj = 0; jj < 4; jj++)
                wmma::load_matrix_sync(bf[jj], &Bs[(wn * 64 + jj * 16) * LDTH + kk], LDTH);
#pragma unroll
            for (int i = 0; i < 2; i++)
#pragma unroll
                for (int jj = 0; jj < 4; jj++)
                    wmma::mma_sync(acc[i][jj], af[i], bf[jj], acc[i][jj]);
        }
    }

#pragma unroll
    for (int i = 0; i < 2; i++)
#pragma unroll
        for (int j = 0; j < 4; j++)
            wmma::store_matrix_sync(
                &C[(size_t)(bm + wm * 32 + i * 16) * N + bn + wn * 64 + j * 16],
                acc[i][j], N, wmma::mem_row_major);
}

// ---------------------------------------------------------------------------
// GEMM2 (split-fp16): C = Ah*Bh^T + Ah*Bl^T + Al*Bh^T, fp32 acc.
// CTA 128x128, 8 warps (4Mx2N), warp tile 32x64. 2-stage ring, K=32/stage.
// ---------------------------------------------------------------------------
constexpr int TKS  = 32;
constexpr int LDSP = 40;
constexpr int STGS = 512 * LDSP;     // halfs per stage
#define SMEM_SP (2 * STGS * 2)       // 81920 bytes

__global__ void __launch_bounds__(256, 2) gemm_sp(const __half* __restrict__ Ah,
                                                  const __half* __restrict__ Al,
                                                  const __half* __restrict__ Bh,
                                                  const __half* __restrict__ Bl,
                                                  float* __restrict__ C,
                                                  int M, int N, int K) {
    extern __shared__ __align__(16) __half sms[];
    const int tid  = threadIdx.x;
    const int warp = tid >> 5;
    const int wm   = warp >> 1, wn = warp & 1;
    const int bm   = blockIdx.y * 128, bn = blockIdx.x * 128;

    wmma::fragment<wmma::accumulator, 16, 16, 16, float> acc[2][4];
#pragma unroll
    for (int i = 0; i < 2; i++)
#pragma unroll
        for (int j = 0; j < 4; j++) wmma::fill_fragment(acc[i][j], 0.0f);

    const int lrow = tid >> 2;          // 0..63
    const int lcol = (tid & 3) << 3;    // 0,8,16,24 halfs (16B chunks)

    auto load_stage = [&](int s, int k0) {
        __half* stg = sms + s * STGS;
#pragma unroll
        for (int t = 0; t < 8; t++) {
            int row = lrow + t * 64;            // 0..511
            int g = row >> 7, r = row & 127;
            const __half* src =
                (g == 0) ? &Ah[(size_t)(bm + r) * K + k0 + lcol]
              : (g == 1) ? &Al[(size_t)(bm + r) * K + k0 + lcol]
              : (g == 2) ? &Bh[(size_t)(bn + r) * K + k0 + lcol]
                         : &Bl[(size_t)(bn + r) * K + k0 + lcol];
            cp_async16(&stg[row * LDSP + lcol], src);
        }
        asm volatile("cp.async.commit_group;\n" ::: "memory");
    };

    load_stage(0, 0);

    const int niter = K / TKS;   // 32
    for (int j = 0; j < niter; j++) {
        if (j + 1 < niter) load_stage((j + 1) & 1, (j + 1) * TKS);
        else asm volatile("cp.async.commit_group;\n" ::: "memory");
        asm volatile("cp.async.wait_group 1;\n" ::: "memory");
        __syncthreads();

        const __half* As_h = sms + (j & 1) * STGS;
        const __half* As_l = As_h + 128 * LDSP;
        const __half* Bs_h = As_h + 256 * LDSP;
        const __half* Bs_l = As_h + 384 * LDSP;
#pragma unroll
        for (int kk = 0; kk < TKS; kk += 16) {
            wmma::fragment<wmma::matrix_a, 16, 16, 16, __half, wmma::row_major> afh[2], afl[2];
#pragma unroll
            for (int i = 0; i < 2; i++) {
                wmma::load_matrix_sync(afh[i], &As_h[(wm * 32 + i * 16) * LDSP + kk], LDSP);
                wmma::load_matrix_sync(afl[i], &As_l[(wm * 32 + i * 16) * LDSP + kk], LDSP);
            }
#pragma unroll
            for (int jj = 0; jj < 4; jj++) {
                wmma::fragment<wmma::matrix_b, 16, 16, 16, __half, wmma::col_major> bfh, bfl;
                wmma::load_matrix_sync(bfh, &Bs_h[(wn * 64 + jj * 16) * LDSP + kk], LDSP);
                wmma::load_matrix_sync(bfl, &Bs_l[(wn * 64 + jj * 16) * LDSP + kk], LDSP);
#pragma unroll
                for (int i = 0; i < 2; i++) {
                    wmma::mma_sync(acc[i][jj], afh[i], bfh, acc[i][jj]);
                    wmma::mma_sync(acc[i][jj], afh[i], bfl, acc[i][jj]);
                    wmma::mma_sync(acc[i][jj], afl[i], bfh, acc[i][jj]);
                }
            }
        }
        __syncthreads();
    }

#pragma unroll
    for (int i = 0; i < 2; i++)
#pragma unroll
        for (int j = 0; j < 4; j++)
            wmma::store_matrix_sync(
                &C[(size_t)(bm + wm * 32 + i * 16) * N + bn + wn * 64 + j * 16],
                acc[i][j], N, wmma::mem_row_major);
}

// ---------------------------------------------------------------------------
// Fused attention v4: latency-chain fixes, numerics IDENTICAL to v3.
//  - LN loads register-batched (36 loads in flight before any reduction)
//  - V loaded via float4 by warps 5-7 during QK^T MMA
//  - bias prefetched into registers BEFORE the post-MMA barrier
// ---------------------------------------------------------------------------
#define LDQH  72
#define LDPH  88
#define LDS2  84
#define ATT_QH 0
#define ATT_KH 11520
#define ATT_VH 23040
#define ATT_PH 34560
#define ATT_S  48640
#define SMEM_ATT3 75520

__global__ void __launch_bounds__(256) attn_kernel(
    const float* __restrict__ qkv, const float* __restrict__ bias,
    const float* __restrict__ bscale_p,
    const float* __restrict__ qn_w, const float* __restrict__ qn_b,
    const float* __restrict__ kn_w, const float* __restrict__ kn_b,
    __half* __restrict__ outh, __half* __restrict__ outl) {
    extern __shared__ __align__(16) char smc[];
    __half* qh  = (__half*)(smc + ATT_QH);
    __half* kh  = (__half*)(smc + ATT_KH);
    __half* vh  = (__half*)(smc + ATT_VH);
    __half* ph  = (__half*)(smc + ATT_PH);
    float*  s_s = (float*)(smc + ATT_S);

    const int tid = threadIdx.x, lane = tid & 31, warp = tid >> 5;
    const int h = blockIdx.x, b = blockIdx.y;
    const float bscale = *bscale_p;
    const size_t base = (size_t)b * SEQ * 3072 + (size_t)h * 64;

    // zero: full P tile + vh pad rows 65..79
    {
        unsigned* phz = (unsigned*)ph;
        for (int i = tid; i < 3520; i += 256) phz[i] = 0u;
        unsigned* vhz = (unsigned*)vh + 65 * (LDQH / 2);
        for (int i = tid; i < 15 * (LDQH / 2); i += 256) vhz[i] = 0u;
    }

    // ---- LN phase: batch ALL gmem loads first (high MLP), then reduce ----
    const float qw0 = qn_w[lane], qw1 = qn_w[lane + 32];
    const float qb0 = qn_b[lane], qb1 = qn_b[lane + 32];
    const float kw0 = kn_w[lane], kw1 = kn_w[lane + 32];
    const float kb0 = kn_b[lane], kb1 = kn_b[lane + 32];

    float xq0[9], xq1[9], xk0[9], xk1[9];
#pragma unroll
    for (int t = 0; t < 9; t++) {
        int n = warp + t * 8;
        if (n < SEQ) {
            const float* row = qkv + base + (size_t)n * 3072;
            xq0[t] = row[lane];
            xq1[t] = row[lane + 32];
            xk0[t] = row[1024 + lane];
            xk1[t] = row[1024 + lane + 32];
        }
    }
#pragma unroll
    for (int t = 0; t < 9; t++) {
        int n = warp + t * 8;
        if (n < SEQ) {
            float x0 = xq0[t], x1 = xq1[t];
            float s = x0 + x1, sq = x0 * x0 + x1 * x1;
#pragma unroll
            for (int o = 16; o; o >>= 1) {
                s += __shfl_xor_sync(0xffffffffu, s, o);
                sq += __shfl_xor_sync(0xffffffffu, sq, o);
            }
            float mu = s * (1.f / 64.f);
            float rstd = rsqrtf(sq * (1.f / 64.f) - mu * mu + 1e-5f);
            qh[n * LDQH + lane]      = __float2half(((x0 - mu) * rstd * qw0 + qb0) * 0.125f);
            qh[n * LDQH + lane + 32] = __float2half(((x1 - mu) * rstd * qw1 + qb1) * 0.125f);

            x0 = xk0[t]; x1 = xk1[t];
            s = x0 + x1; sq = x0 * x0 + x1 * x1;
#pragma unroll
            for (int o = 16; o; o >>= 1) {
                s += __shfl_xor_sync(0xffffffffu, s, o);
                sq += __shfl_xor_sync(0xffffffffu, sq, o);
            }
            mu = s * (1.f / 64.f);
            rstd = rsqrtf(sq * (1.f / 64.f) - mu * mu + 1e-5f);
            kh[n * LDQH + lane]      = __float2half((x0 - mu) * rstd * kw0 + kb0);
            kh[n * LDQH + lane + 32] = __float2half((x1 - mu) * rstd * kw1 + kb1);
        }
    }
    __syncthreads();

    // ---- S = Q K^T (warps 0-4); warps 5-7 load V via float4 ----
    if (warp < 5) {
        wmma::fragment<wmma::accumulator, 16, 16, 16, float> sacc[5];
#pragma unroll
        for (int m = 0; m < 5; m++) wmma::fill_fragment(sacc[m], 0.0f);
#pragma unroll
        for (int kk = 0; kk < 4; kk++) {
            wmma::fragment<wmma::matrix_a, 16, 16, 16, __half, wmma::row_major> aq;
            wmma::load_matrix_sync(aq, &qh[warp * 16 * LDQH + kk * 16], LDQH);
#pragma unroll
            for (int m = 0; m < 5; m++) {
                wmma::fragment<wmma::matrix_b, 16, 16, 16, __half, wmma::col_major> bk;
                wmma::load_matrix_sync(bk, &kh[m * 16 * LDQH + kk * 16], LDQH);
                wmma::mma_sync(sacc[m], aq, bk, sacc[m]);
            }
        }
#pragma unroll
        for (int m = 0; m < 5; m++)
            wmma::store_matrix_sync(&s_s[warp * 16 * LDS2 + m * 16], sacc[m],
                                    LDS2, wmma::mem_row_major);
    } else {
        // 65 rows x 16 float4 = 1040 chunks over 96 threads (unrolled, MLP high)
#pragma unroll
        for (int t = 0; t < 11; t++) {
            int i = (tid - 160) + t * 96;
            if (i < SEQ * 16) {
                int n = i >> 4, d4 = (i & 15) << 2;
                float4 v = *(const float4*)&qkv[base + (size_t)n * 3072 + 2048 + d4];
                *(__half2*)&vh[n * LDQH + d4]     = __floats2half2_rn(v.x, v.y);
                *(__half2*)&vh[n * LDQH + d4 + 2] = __floats2half2_rn(v.z, v.w);
            }
        }
    }

    // ---- prefetch bias into registers BEFORE waiting on the MMA barrier ----
    float bp0[9], bp1[9], bp2[9];
#pragma unroll
    for (int t = 0; t < 9; t++) {
        int n = warp + t * 8;
        if (n < SEQ) {
            const float* brow = &bias[((size_t)h * SEQ + n) * SEQ];
            bp0[t] = brow[lane];
            bp1[t] = brow[lane + 32];
            bp2[t] = (lane == 0) ? brow[64] : 0.f;
        }
    }
    __syncthreads();

    // ---- softmax rows (fp32, bias from registers); write P as half ----
#pragma unroll
    for (int t = 0; t < 9; t++) {
        int n = warp + t * 8;
        if (n < SEQ) {
            float v0 = s_s[n * LDS2 + lane]      + bp0[t] * bscale;
            float v1 = s_s[n * LDS2 + lane + 32] + bp1[t] * bscale;
            float v2 = (lane == 0) ? s_s[n * LDS2 + 64] + bp2[t] * bscale : -3.4e38f;
            float mx = fmaxf(fmaxf(v0, v1), v2);
#pragma unroll
            for (int o = 16; o; o >>= 1)
                mx = fmaxf(mx, __shfl_xor_sync(0xffffffffu, mx, o));
            float e0 = __expf(v0 - mx), e1 = __expf(v1 - mx);
            float e2 = (lane == 0) ? __expf(v2 - mx) : 0.f;
            float sum = e0 + e1 + e2;
#pragma unroll
            for (int o = 16; o; o >>= 1) sum += __shfl_xor_sync(0xffffffffu, sum, o);
            float inv = 1.f / sum;
            ph[n * LDPH + lane]      = __float2half(e0 * inv);
            ph[n * LDPH + lane + 32] = __float2half(e1 * inv);
            if (lane == 0) ph[n * LDPH + 64] = __float2half(e2 * inv);
        }
    }
    __syncthreads();

    // ---- O = P V on tensor cores (warps 0-4) ----
    if (warp < 5) {
        wmma::fragment<wmma::accumulator, 16, 16, 16, float> oacc[4];
#pragma unroll
        for (int j = 0; j < 4; j++) wmma::fill_fragment(oacc[j], 0.0f);
#pragma unroll
        for (int kk = 0; kk < 5; kk++) {
            wmma::fragment<wmma::matrix_a, 16, 16, 16, __half, wmma::row_major> ap;
            wmma::load_matrix_sync(ap, &ph[warp * 16 * LDPH + kk * 16], LDPH);
#pragma unroll
            for (int j = 0; j < 4; j++) {
                wmma::fragment<wmma::matrix_b, 16, 16, 16, __half, wmma::row_major> bv;
                wmma::load_matrix_sync(bv, &vh[kk * 16 * LDQH + j * 16], LDQH);
                wmma::mma_sync(oacc[j], ap, bv, oacc[j]);
            }
        }
#pragma unroll
        for (int j = 0; j < 4; j++)
            wmma::store_matrix_sync(&s_s[warp * 16 * LDS2 + j * 16], oacc[j],
                                    LDS2, wmma::mem_row_major);
    }
    __syncthreads();

    // ---- epilogue: split-fp16 write (hi, lo) -> feeds split GEMM2 ----
    for (int i = tid; i < SEQ * 64; i += 256) {
        int n = i >> 6, d = i & 63;
        float v = s_s[n * LDS2 + d];
        __half hh = __float2half_rn(v);
        __half ll = __float2half_rn(v - __half2float(hh));
        size_t o = ((size_t)b * SEQ + n) * DIMC + (size_t)h * 64 + d;
        outh[o] = hh;
        outl[o] = ll;
    }
}

// ---------------------------------------------------------------------------
extern "C" void kernel_launch(void* const* d_in, const int* in_sizes, int n_in,
                              void* d_out, int out_size) {
    const float* x      = (const float*)d_in[0];
    const float* w_qkv  = (const float*)d_in[1];
    const float* w_proj = (const float*)d_in[2];
    const float* qn_w   = (const float*)d_in[3];
    const float* qn_b   = (const float*)d_in[4];
    const float* kn_w   = (const float*)d_in[5];
    const float* kn_b   = (const float*)d_in[6];
    const float* bias   = (const float*)d_in[7];
    const float* bscale = (const float*)d_in[8];
    float* out          = (float*)d_out;

    float* qkv_p;
    __half *xh_p, *wqkvh_p, *oh_p, *ol_p, *wph_p, *wpl_p;
    cudaGetSymbolAddress((void**)&qkv_p, g_qkv);
    cudaGetSymbolAddress((void**)&xh_p, g_xh);
    cudaGetSymbolAddress((void**)&wqkvh_p, g_wqkvh);
    cudaGetSymbolAddress((void**)&oh_p, g_oh);
    cudaGetSymbolAddress((void**)&ol_p, g_ol);
    cudaGetSymbolAddress((void**)&wph_p, g_wph);
    cudaGetSymbolAddress((void**)&wpl_p, g_wpl);

    cudaFuncSetAttribute(gemm_h, cudaFuncAttributeMaxDynamicSharedMemorySize,
                         SMEM_GH);
    cudaFuncSetAttribute(gemm_sp, cudaFuncAttributeMaxDynamicSharedMemorySize,
                         SMEM_SP);
    cudaFuncSetAttribute(attn_kernel, cudaFuncAttributeMaxDynamicSharedMemorySize,
                         SMEM_ATT3);

    // 0) operand converts: fp16 for GEMM1; split-fp16 for w_proj
    int n4x = MROWS * DIMC / 4;
    f2h_k<<<(n4x + 255) / 256, 256>>>((const float4*)x, (__half2*)xh_p, n4x);
    int n4wq = 3 * DIMC * DIMC / 4;
    f2h_k<<<(n4wq + 255) / 256, 256>>>((const float4*)w_qkv, (__half2*)wqkvh_p, n4wq);
    int n4wp = DIMC * DIMC / 4;
    f2hsplit_k<<<(n4wp + 255) / 256, 256>>>((const float4*)w_proj,
                                            (__half2*)wph_p, (__half2*)wpl_p, n4wp);

    // 1) QKV projection (fp16 tensor): [33280,1024] x [3072,1024]^T
    gemm_h<<<dim3(3 * DIMC / 128, MROWS / 128), 256, SMEM_GH>>>(
        xh_p, wqkvh_p, qkv_p, MROWS, 3 * DIMC, DIMC);
    // 2) Fused LN + attention per (b,h); writes split-fp16 output
    attn_kernel<<<dim3(HEADS, BATCH), 256, SMEM_ATT3>>>(
        qkv_p, bias, bscale, qn_w, qn_b, kn_w, kn_b, oh_p, ol_p);
    // 3) Output projection (split-fp16, 3-term): [33280,1024] x [1024,1024]^T
    gemm_sp<<<dim3(DIMC / 128, MROWS / 128), 256, SMEM_SP>>>(
        oh_p, ol_p, wph_p, wpl_p, out, MROWS, DIMC, DIMC);
}